// round 6
// baseline (speedup 1.0000x reference)
#include <cuda_runtime.h>

#define NN 50000
#define NE 800000
#define NG 256
#define LRELU(v) ((v) >= 0.f ? (v) : 0.01f * (v))

// ---------------- scratch (static device allocations; no cudaMalloc) ----------------
__device__ int   g_deg[NN];
__device__ int   g_off[NN + 1];
__device__ int   g_cursor[NN];
__device__ int   g_perm[NE];
__device__ int   g_gcount[NG];
__device__ int   g_goff[NG + 1];
__device__ float g_h1[(size_t)NN * 64];
__device__ float g_aggr64[(size_t)NN * 64];
__device__ float g_t256[(size_t)NN * 256];     // enc projection, later reused as latent-aggregate
__device__ float g_aggr256[(size_t)NN * 256];
__device__ float g_latent[(size_t)NN * 256];
__device__ float g_pooled[NG * 256];

// ---------------- CSR construction ----------------
__global__ void k_zero_counts() {
    int i = blockIdx.x * blockDim.x + threadIdx.x;
    if (i < NN) g_deg[i] = 0;
    if (i < NG) g_gcount[i] = 0;
}

__global__ void k_hist_edges(const int* __restrict__ dst) {
    int e = blockIdx.x * blockDim.x + threadIdx.x;
    if (e < NE) atomicAdd(&g_deg[dst[e]], 1);
}

__global__ void k_hist_nodes(const int* __restrict__ batch) {
    int i = blockIdx.x * blockDim.x + threadIdx.x;
    if (i < NN) atomicAdd(&g_gcount[batch[i]], 1);
}

// single-block scan over 50000 counts -> offsets (exclusive, g_off[0]=0, g_off[NN]=NE)
__global__ void k_scan_nodes() {
    __shared__ int s[1024];
    __shared__ int carry;
    int t = threadIdx.x;
    if (t == 0) carry = 0;
    __syncthreads();
    for (int base = 0; base < NN; base += 1024) {
        int idx = base + t;
        int v = (idx < NN) ? g_deg[idx] : 0;
        s[t] = v;
        __syncthreads();
        for (int off = 1; off < 1024; off <<= 1) {
            int tv = (t >= off) ? s[t - off] : 0;
            __syncthreads();
            s[t] += tv;
            __syncthreads();
        }
        if (idx < NN) g_off[idx + 1] = carry + s[t];
        __syncthreads();
        if (t == 0) carry += s[1023];
        __syncthreads();
    }
    if (t == 0) g_off[0] = 0;
}

__global__ void k_scan_graphs() {
    __shared__ int s[NG];
    int t = threadIdx.x;
    s[t] = g_gcount[t];
    __syncthreads();
    for (int off = 1; off < NG; off <<= 1) {
        int tv = (t >= off) ? s[t - off] : 0;
        __syncthreads();
        s[t] += tv;
        __syncthreads();
    }
    g_goff[t + 1] = s[t];
    if (t == 0) g_goff[0] = 0;
}

__global__ void k_copy_cursor() {
    int i = blockIdx.x * blockDim.x + threadIdx.x;
    if (i < NN) g_cursor[i] = g_off[i];
}

__global__ void k_scatter(const int* __restrict__ src, const int* __restrict__ dst) {
    int e = blockIdx.x * blockDim.x + threadIdx.x;
    if (e < NE) {
        int d = dst[e];
        int p = atomicAdd(&g_cursor[d], 1);
        g_perm[p] = src[e];
    }
}

// ---------------- conv1: emb lookup + 3-wide aggregate + [3->64] linears, fused ----------------
__global__ void k_conv1(const int* __restrict__ x, const float* __restrict__ emb,
                        const float* __restrict__ w_rel, const float* __restrict__ w_root,
                        const float* __restrict__ b1) {
    int i = blockIdx.x;
    int t = threadIdx.x;  // 64
    __shared__ float embs[30];
    __shared__ float aggr[3];
    if (t < 30) embs[t] = emb[t];
    __syncthreads();
    if (t < 3) {
        float a = 0.f;
        int s0 = g_off[i], s1 = g_off[i + 1];
        for (int e = s0; e < s1; e++) {
            int s = g_perm[e];
            a += embs[x[s] * 3 + t];
        }
        aggr[t] = a;
    }
    __syncthreads();
    int lab = x[i];
    float v = b1[t];
#pragma unroll
    for (int c = 0; c < 3; c++)
        v += aggr[c] * w_rel[c * 64 + t] + embs[lab * 3 + c] * w_root[c * 64 + t];
    g_h1[(size_t)i * 64 + t] = LRELU(v);
}

// ---------------- aggregations (gather via CSR) ----------------
__global__ void k_agg64() {  // one warp per node, float2 lanes
    int w = threadIdx.x >> 5;
    int lane = threadIdx.x & 31;
    int i = blockIdx.x * 4 + w;
    if (i >= NN) return;
    const float2* h = reinterpret_cast<const float2*>(g_h1);
    float2 acc = make_float2(0.f, 0.f);
    int s0 = g_off[i], s1 = g_off[i + 1];
    for (int e = s0; e < s1; e++) {
        int s = g_perm[e];
        float2 v = h[(size_t)s * 32 + lane];
        acc.x += v.x;
        acc.y += v.y;
    }
    reinterpret_cast<float2*>(g_aggr64)[(size_t)i * 32 + lane] = acc;
}

__global__ void k_agg256(const float* __restrict__ in, float* __restrict__ outp) {
    int i = blockIdx.x;
    int t = threadIdx.x;  // 256
    int s0 = g_off[i], s1 = g_off[i + 1];
    float acc = 0.f;
    for (int e = s0; e < s1; e++) {
        int s = g_perm[e];
        acc += in[(size_t)s * 256 + t];
    }
    outp[(size_t)i * 256 + t] = acc;
}

// ---------------- fused GEMM: out = act(A1@W1 [+ A2@W2] [+ Cadd] [+ bias]) ----------------
// 128x128 tile, BK=8, 256 threads, 8x8 microtile, fp32 FFMA
__global__ __launch_bounds__(256, 2) void fused_gemm(
    const float* __restrict__ A1, const float* __restrict__ W1,
    const float* __restrict__ A2, const float* __restrict__ W2,
    const float* __restrict__ Cadd, const float* __restrict__ bias,
    float* __restrict__ out, int M, int N, int K, int act) {
    __shared__ float As[8][128];
    __shared__ float Bs[8][128];
    int bm = blockIdx.y * 128, bn = blockIdx.x * 128;
    int tid = threadIdx.x;
    int tr = tid >> 4, tc = tid & 15;
    int row0 = tr * 8, col0 = tc * 8;
    float acc[8][8];
#pragma unroll
    for (int i = 0; i < 8; i++)
#pragma unroll
        for (int j = 0; j < 8; j++) acc[i][j] = 0.f;

    int aRow = tid >> 1;
    int aCol = (tid & 1) << 2;
    int bCol = tid & 127;
    int bRow = tid >> 7;
    int nparts = A2 ? 2 : 1;

    for (int part = 0; part < nparts; part++) {
        const float* A = part ? A2 : A1;
        const float* B = part ? W2 : W1;
        for (int k0 = 0; k0 < K; k0 += 8) {
            int gr = bm + aRow;
            float4 av = make_float4(0.f, 0.f, 0.f, 0.f);
            if (gr < M) av = *reinterpret_cast<const float4*>(&A[(size_t)gr * K + k0 + aCol]);
            As[aCol + 0][aRow] = av.x;
            As[aCol + 1][aRow] = av.y;
            As[aCol + 2][aRow] = av.z;
            As[aCol + 3][aRow] = av.w;
#pragma unroll
            for (int r = 0; r < 4; r++) {
                int kk = bRow + r * 2;
                Bs[kk][bCol] = B[(size_t)(k0 + kk) * N + bn + bCol];
            }
            __syncthreads();
#pragma unroll
            for (int k = 0; k < 8; k++) {
                float a[8], b[8];
                *reinterpret_cast<float4*>(&a[0]) = *reinterpret_cast<const float4*>(&As[k][row0]);
                *reinterpret_cast<float4*>(&a[4]) = *reinterpret_cast<const float4*>(&As[k][row0 + 4]);
                *reinterpret_cast<float4*>(&b[0]) = *reinterpret_cast<const float4*>(&Bs[k][col0]);
                *reinterpret_cast<float4*>(&b[4]) = *reinterpret_cast<const float4*>(&Bs[k][col0 + 4]);
#pragma unroll
                for (int i = 0; i < 8; i++)
#pragma unroll
                    for (int j = 0; j < 8; j++) acc[i][j] = fmaf(a[i], b[j], acc[i][j]);
            }
            __syncthreads();
        }
    }

#pragma unroll
    for (int i = 0; i < 8; i++) {
        int r = bm + row0 + i;
        if (r >= M) continue;
#pragma unroll
        for (int j = 0; j < 8; j += 4) {
            int c = bn + col0 + j;
            float4 v = make_float4(acc[i][j], acc[i][j + 1], acc[i][j + 2], acc[i][j + 3]);
            if (Cadd) {
                float4 cv = *reinterpret_cast<const float4*>(&Cadd[(size_t)r * N + c]);
                v.x += cv.x; v.y += cv.y; v.z += cv.z; v.w += cv.w;
            }
            if (bias) {
                v.x += bias[c]; v.y += bias[c + 1]; v.z += bias[c + 2]; v.w += bias[c + 3];
            }
            if (act) {
                v.x = LRELU(v.x); v.y = LRELU(v.y); v.z = LRELU(v.z); v.w = LRELU(v.w);
            }
            *reinterpret_cast<float4*>(&out[(size_t)r * N + c]) = v;
        }
    }
}

// ---------------- pooling + logits ----------------
__global__ void k_pool() {
    int g = blockIdx.x;
    int t = threadIdx.x;  // 256
    int s0 = g_goff[g], s1 = g_goff[g + 1];
    float acc = 0.f;
    for (int n = s0; n < s1; n++) acc += g_latent[(size_t)n * 256 + t];
    float cnt = (float)(s1 - s0);
    if (cnt < 1.f) cnt = 1.f;
    g_pooled[g * 256 + t] = acc / cnt;
}

__global__ void k_logits(const float* __restrict__ w_lin, const float* __restrict__ b_lin,
                         float* __restrict__ out) {
    int idx = blockIdx.x * blockDim.x + threadIdx.x;
    if (idx >= NG * 7) return;
    int g = idx / 7, o = idx % 7;
    float acc = b_lin[o];
    for (int k = 0; k < 256; k++) acc += g_pooled[g * 256 + k] * w_lin[k * 7 + o];
    out[g * 7 + o] = acc;
}

// ---------------- launch ----------------
extern "C" void kernel_launch(void* const* d_in, const int* in_sizes, int n_in,
                              void* d_out, int out_size) {
    const int*   x       = (const int*)d_in[0];
    const int*   ei      = (const int*)d_in[1];
    const int*   batch   = (const int*)d_in[2];
    const float* emb     = (const float*)d_in[3];
    const float* w1_rel  = (const float*)d_in[4];
    const float* w1_root = (const float*)d_in[5];
    const float* b1      = (const float*)d_in[6];
    const float* w2_rel  = (const float*)d_in[7];
    const float* w2_root = (const float*)d_in[8];
    const float* b2      = (const float*)d_in[9];
    const float* we_rel  = (const float*)d_in[10];
    const float* we_root = (const float*)d_in[11];
    const float* be      = (const float*)d_in[12];
    const float* wd_rel  = (const float*)d_in[13];
    const float* wd_root = (const float*)d_in[14];
    const float* bd      = (const float*)d_in[15];
    const float* w_lin   = (const float*)d_in[16];
    const float* b_lin   = (const float*)d_in[17];

    const int* src = ei;
    const int* dst = ei + NE;

    float* out_f   = (float*)d_out;
    float* logits  = out_f;
    float* recon   = out_f + NG * 7;
    float* orig    = out_f + NG * 7 + (size_t)NN * 1024;

    // CSR + graph offsets
    k_zero_counts<<<(NN + 255) / 256, 256>>>();
    k_hist_edges<<<(NE + 255) / 256, 256>>>(dst);
    k_hist_nodes<<<(NN + 255) / 256, 256>>>(batch);
    k_scan_nodes<<<1, 1024>>>();
    k_scan_graphs<<<1, NG>>>();
    k_copy_cursor<<<(NN + 255) / 256, 256>>>();
    k_scatter<<<(NE + 255) / 256, 256>>>(src, dst);

    // conv1: [N,3] -> h1 [N,64]
    k_conv1<<<NN, 64>>>(x, emb, w1_rel, w1_root, b1);

    // conv2: aggregate h1, then [N,64|64] x [64,1024] fused -> original
    k_agg64<<<(NN + 3) / 4, 128>>>();
    {
        float* a64 = nullptr; float* h1 = nullptr;
        cudaGetSymbolAddress((void**)&a64, g_aggr64);
        cudaGetSymbolAddress((void**)&h1, g_h1);
        fused_gemm<<<dim3(1024 / 128, (NN + 127) / 128), 256>>>(
            a64, w2_rel, h1, w2_root, nullptr, b2, orig, NN, 1024, 64, 1);
    }

    // enc: project first (original @ we_rel -> t256), aggregate at 256, then
    // latent = lrelu(original @ we_root + aggr + be)
    {
        float* t256 = nullptr; float* a256 = nullptr; float* lat = nullptr;
        cudaGetSymbolAddress((void**)&t256, g_t256);
        cudaGetSymbolAddress((void**)&a256, g_aggr256);
        cudaGetSymbolAddress((void**)&lat, g_latent);

        fused_gemm<<<dim3(256 / 128, (NN + 127) / 128), 256>>>(
            orig, we_rel, nullptr, nullptr, nullptr, nullptr, t256, NN, 256, 1024, 0);
        k_agg256<<<NN, 256>>>(t256, a256);
        fused_gemm<<<dim3(256 / 128, (NN + 127) / 128), 256>>>(
            orig, we_root, nullptr, nullptr, a256, be, lat, NN, 256, 1024, 1);

        // dec: aggregate latent at 256 (reuse t256), then [N,256|256] x [256,1024] -> reconstructed
        k_agg256<<<NN, 256>>>(lat, t256);
        fused_gemm<<<dim3(1024 / 128, (NN + 127) / 128), 256>>>(
            t256, wd_rel, lat, wd_root, nullptr, bd, recon, NN, 1024, 256, 1);
    }

    // pooling + logits
    k_pool<<<NG, 256>>>();
    k_logits<<<(NG * 7 + 255) / 256, 256>>>(w_lin, b_lin, logits);
}

// round 8
// speedup vs baseline: 1.7236x; 1.7236x over previous
#include <cuda_runtime.h>
#include <cuda_bf16.h>
#include <cstdint>

#define NN 50000
#define NE 800000
#define NG 256
#define LRELU(v) ((v) >= 0.f ? (v) : 0.01f * (v))

// ---------------- scratch (static device allocations; no cudaMalloc) ----------------
__device__ int   g_deg[NN];
__device__ int   g_off[NN + 1];
__device__ int   g_cursor[NN];
__device__ int   g_perm[NE];
__device__ int   g_gcount[NG];
__device__ int   g_goff[NG + 1];
__device__ float g_h1[(size_t)NN * 64];
__device__ float g_aggr64[(size_t)NN * 64];
__device__ float g_enc[(size_t)NN * 512];      // enc GEMM out: cols 0-255 rel-proj, 256-511 root-proj
__device__ float g_aggr256[(size_t)NN * 256];
__device__ float g_latent[(size_t)NN * 256];
__device__ float g_aggdec[(size_t)NN * 256];
__device__ float g_pooled[NG * 256];
// transposed + bf16-split weights (K-major: [N, Ktot])
__device__ __nv_bfloat16 g_Bc2h[1024 * 128], g_Bc2l[1024 * 128];
__device__ __nv_bfloat16 g_Beh[512 * 1024],  g_Bel[512 * 1024];
__device__ __nv_bfloat16 g_Bdh[1024 * 512],  g_Bdl[1024 * 512];

// ---------------- helpers ----------------
__device__ __forceinline__ uint32_t smem_u32(const void* p) {
    uint32_t a;
    asm("{ .reg .u64 t; cvta.to.shared.u64 t, %1; cvt.u32.u64 %0, t; }" : "=r"(a) : "l"(p));
    return a;
}
__device__ __forceinline__ void ldsm_x4(uint32_t& r0, uint32_t& r1, uint32_t& r2, uint32_t& r3,
                                        uint32_t addr) {
    asm volatile("ldmatrix.sync.aligned.m8n8.x4.shared.b16 {%0,%1,%2,%3}, [%4];"
                 : "=r"(r0), "=r"(r1), "=r"(r2), "=r"(r3) : "r"(addr));
}
__device__ __forceinline__ void mma_bf16(float* c, const uint32_t* a, const uint32_t* b) {
    asm volatile(
        "mma.sync.aligned.m16n8k16.row.col.f32.bf16.bf16.f32 "
        "{%0,%1,%2,%3}, {%4,%5,%6,%7}, {%8,%9}, {%0,%1,%2,%3};"
        : "+f"(c[0]), "+f"(c[1]), "+f"(c[2]), "+f"(c[3])
        : "r"(a[0]), "r"(a[1]), "r"(a[2]), "r"(a[3]), "r"(b[0]), "r"(b[1]));
}
__device__ __forceinline__ void split1(float a, __nv_bfloat16& h, __nv_bfloat16& l) {
    h = __float2bfloat16(a);
    l = __float2bfloat16(a - __bfloat162float(h));
}

// ---------------- CSR construction ----------------
__global__ void k_zero_counts() {
    int i = blockIdx.x * blockDim.x + threadIdx.x;
    if (i < NN) g_deg[i] = 0;
    if (i < NG) g_gcount[i] = 0;
}
__global__ void k_hist_edges(const int* __restrict__ dst) {
    int e = blockIdx.x * blockDim.x + threadIdx.x;
    if (e < NE) atomicAdd(&g_deg[dst[e]], 1);
}
__global__ void k_hist_nodes(const int* __restrict__ batch) {
    int i = blockIdx.x * blockDim.x + threadIdx.x;
    if (i < NN) atomicAdd(&g_gcount[batch[i]], 1);
}
// shuffle-based single-block scan over 50000 counts
__global__ void k_scan_nodes() {
    __shared__ int wsum[32];
    __shared__ int carry;
    int t = threadIdx.x, lane = t & 31, w = t >> 5;
    if (t == 0) carry = 0;
    __syncthreads();
    for (int base = 0; base < NN; base += 1024) {
        int idx = base + t;
        int v = (idx < NN) ? g_deg[idx] : 0;
        int sc = v;
#pragma unroll
        for (int o = 1; o < 32; o <<= 1) { int u = __shfl_up_sync(~0u, sc, o); if (lane >= o) sc += u; }
        if (lane == 31) wsum[w] = sc;
        __syncthreads();
        if (w == 0) {
            int s = wsum[lane];
#pragma unroll
            for (int o = 1; o < 32; o <<= 1) { int u = __shfl_up_sync(~0u, s, o); if (lane >= o) s += u; }
            wsum[lane] = s;
        }
        __syncthreads();
        int pre = (w > 0) ? wsum[w - 1] : 0;
        if (idx < NN) g_off[idx + 1] = carry + pre + sc;
        __syncthreads();
        if (t == 0) carry += wsum[31];
        __syncthreads();
    }
    if (t == 0) g_off[0] = 0;
}
__global__ void k_scan_graphs() {
    __shared__ int s[NG];
    int t = threadIdx.x;
    s[t] = g_gcount[t];
    __syncthreads();
    for (int off = 1; off < NG; off <<= 1) {
        int tv = (t >= off) ? s[t - off] : 0;
        __syncthreads();
        s[t] += tv;
        __syncthreads();
    }
    g_goff[t + 1] = s[t];
    if (t == 0) g_goff[0] = 0;
}
__global__ void k_copy_cursor() {
    int i = blockIdx.x * blockDim.x + threadIdx.x;
    if (i < NN) g_cursor[i] = g_off[i];
}
__global__ void k_scatter(const int* __restrict__ src, const int* __restrict__ dst) {
    int e = blockIdx.x * blockDim.x + threadIdx.x;
    if (e < NE) {
        int d = dst[e];
        int p = atomicAdd(&g_cursor[d], 1);
        g_perm[p] = src[e];
    }
}

// ---------------- conv1 ----------------
__global__ void k_conv1(const int* __restrict__ x, const float* __restrict__ emb,
                        const float* __restrict__ w_rel, const float* __restrict__ w_root,
                        const float* __restrict__ b1) {
    int i = blockIdx.x;
    int t = threadIdx.x;  // 64
    __shared__ float embs[30];
    __shared__ float aggr[3];
    if (t < 30) embs[t] = emb[t];
    __syncthreads();
    if (t < 3) {
        float a = 0.f;
        int s0 = g_off[i], s1 = g_off[i + 1];
        for (int e = s0; e < s1; e++) a += embs[x[g_perm[e]] * 3 + t];
        aggr[t] = a;
    }
    __syncthreads();
    int lab = x[i];
    float v = b1[t];
#pragma unroll
    for (int c = 0; c < 3; c++)
        v += aggr[c] * w_rel[c * 64 + t] + embs[lab * 3 + c] * w_root[c * 64 + t];
    g_h1[(size_t)i * 64 + t] = LRELU(v);
}

// ---------------- aggregations ----------------
__global__ void k_agg64() {
    int w = threadIdx.x >> 5, lane = threadIdx.x & 31;
    int i = blockIdx.x * 4 + w;
    if (i >= NN) return;
    const float2* h = reinterpret_cast<const float2*>(g_h1);
    float2 acc = make_float2(0.f, 0.f);
    int s0 = g_off[i], s1 = g_off[i + 1];
    for (int e = s0; e < s1; e++) {
        float2 v = h[(size_t)g_perm[e] * 32 + lane];
        acc.x += v.x;
        acc.y += v.y;
    }
    reinterpret_cast<float2*>(g_aggr64)[(size_t)i * 32 + lane] = acc;
}
__global__ void k_agg256(const float* __restrict__ in, int ldin, float* __restrict__ outp) {
    int i = blockIdx.x;
    int t = threadIdx.x;  // 256
    int s0 = g_off[i], s1 = g_off[i + 1];
    float acc = 0.f;
    for (int e = s0; e < s1; e++) acc += in[(size_t)g_perm[e] * ldin + t];
    outp[(size_t)i * 256 + t] = acc;
}
__global__ void k_enc_finish(const float* __restrict__ be) {
    int idx = blockIdx.x * blockDim.x + threadIdx.x;
    if (idx >= NN * 256) return;
    int i = idx >> 8, c = idx & 255;
    float v = g_enc[(size_t)i * 512 + 256 + c] + g_aggr256[idx] + be[c];
    g_latent[idx] = LRELU(v);
}

// ---------------- weight transpose + bf16 split ----------------
// dst [Ntot, Ktot] bf16 hi/lo, K-major. mode 0: K-concat (s1 [split,Ntot], s2 [Ktot-split,Ntot])
// mode 1: N-concat (s1 [Ktot, split], s2 [Ktot, Ntot-split])
__global__ void k_prep(const float* __restrict__ s1, const float* __restrict__ s2,
                       int Ktot, int Ntot, int split, int mode,
                       __nv_bfloat16* __restrict__ dh, __nv_bfloat16* __restrict__ dl) {
    __shared__ float tile[32][33];
    int k0 = blockIdx.x * 32, n0 = blockIdx.y * 32;
    int tx = threadIdx.x, ty = threadIdx.y;  // (32, 8)
#pragma unroll
    for (int r = 0; r < 32; r += 8) {
        int k = k0 + ty + r, n = n0 + tx;
        float v;
        if (mode == 0)
            v = (k < split) ? s1[(size_t)k * Ntot + n] : s2[(size_t)(k - split) * Ntot + n];
        else
            v = (n < split) ? s1[(size_t)k * split + n] : s2[(size_t)k * (Ntot - split) + (n - split)];
        tile[ty + r][tx] = v;
    }
    __syncthreads();
#pragma unroll
    for (int r = 0; r < 32; r += 8) {
        int n = n0 + ty + r, k = k0 + tx;
        float v = tile[tx][ty + r];
        __nv_bfloat16 h, l;
        split1(v, h, l);
        dh[(size_t)n * Ktot + k] = h;
        dl[(size_t)n * Ktot + k] = l;
    }
}

// ---------------- HMMA bf16x3 GEMM ----------------
// out[M,N] = act( [A1|A2][M,Ktot] @ B^T + bias ),  B K-major [N,Ktot] bf16 hi/lo.
// Block 128x128, BK=32, 256 thr, warps 4(m) x 2(n), warp tile 32x64.
// 3-term compensated product: Ah*Bh + Ah*Bl + Al*Bh.
#define BM 128
#define BN 128
#define BK 32
#define BKP 40   // padded K stride (elements) -> 80B rows, ldmatrix conflict-free

__global__ __launch_bounds__(256, 1) void gemm_tc(
    const float* __restrict__ A1, int lda1, const float* __restrict__ A2, int lda2, int K1,
    const __nv_bfloat16* __restrict__ Bh, const __nv_bfloat16* __restrict__ Bl,
    const float* __restrict__ bias, float* __restrict__ out,
    int M, int N, int Ktot, int act) {
    __shared__ __align__(16) __nv_bfloat16 sAh[BM * BKP];
    __shared__ __align__(16) __nv_bfloat16 sAl[BM * BKP];
    __shared__ __align__(16) __nv_bfloat16 sBh[BN * BKP];
    __shared__ __align__(16) __nv_bfloat16 sBl[BN * BKP];

    int tid = threadIdx.x, lane = tid & 31, wid = tid >> 5;
    int wm = wid & 3, wn = wid >> 2;
    int m_base = wm * 32, n_base = wn * 64;
    int bm = blockIdx.y * BM, bn = blockIdx.x * BN;

    uint32_t uAh = smem_u32(sAh), uAl = smem_u32(sAl);
    uint32_t uBh = smem_u32(sBh), uBl = smem_u32(sBl);

    float acc[2][8][4];
#pragma unroll
    for (int i = 0; i < 2; i++)
#pragma unroll
        for (int j = 0; j < 8; j++)
#pragma unroll
            for (int q = 0; q < 4; q++) acc[i][j][q] = 0.f;

    // staging maps: 2 threads per row
    int ldRow = tid >> 1;
    int ldCol = (tid & 1) * 16;

    // ldmatrix lane address components (element offsets within tile)
    int a_row = (lane & 15);
    int a_coff = (lane >> 4) * 8;
    int b_row = ((lane >> 4) << 3) + (lane & 7);
    int b_coff = ((lane >> 3) & 1) * 8;

    int nst = Ktot / BK;
    for (int s = 0; s < nst; s++) {
        int k0 = s * BK;
        __syncthreads();
        // ---- stage A [128 x 32] fp32 -> bf16 hi/lo
        {
            const float* A; int lda; int kc;
            if (k0 < K1) { A = A1; lda = lda1; kc = k0; } else { A = A2; lda = lda2; kc = k0 - K1; }
            int gm = bm + ldRow;
            bool ok = (gm < M);
            const float4* src = reinterpret_cast<const float4*>(A + (size_t)gm * lda + kc + ldCol);
            __nv_bfloat162* dh = reinterpret_cast<__nv_bfloat162*>(&sAh[ldRow * BKP + ldCol]);
            __nv_bfloat162* dl = reinterpret_cast<__nv_bfloat162*>(&sAl[ldRow * BKP + ldCol]);
#pragma unroll
            for (int i = 0; i < 4; i++) {
                float4 v = ok ? src[i] : make_float4(0.f, 0.f, 0.f, 0.f);
                __nv_bfloat16 hx, lx, hy, ly, hz, lz, hw, lw;
                split1(v.x, hx, lx); split1(v.y, hy, ly);
                split1(v.z, hz, lz); split1(v.w, hw, lw);
                dh[i * 2 + 0] = __halves2bfloat162(hx, hy);
                dh[i * 2 + 1] = __halves2bfloat162(hz, hw);
                dl[i * 2 + 0] = __halves2bfloat162(lx, ly);
                dl[i * 2 + 1] = __halves2bfloat162(lz, lw);
            }
        }
        // ---- stage B [128 x 32] bf16 hi/lo (pre-split)
        {
            const uint4* sh = reinterpret_cast<const uint4*>(Bh + (size_t)(bn + ldRow) * Ktot + k0 + ldCol);
            const uint4* sl = reinterpret_cast<const uint4*>(Bl + (size_t)(bn + ldRow) * Ktot + k0 + ldCol);
            uint4* dh = reinterpret_cast<uint4*>(&sBh[ldRow * BKP + ldCol]);
            uint4* dl = reinterpret_cast<uint4*>(&sBl[ldRow * BKP + ldCol]);
            dh[0] = sh[0]; dh[1] = sh[1];
            dl[0] = sl[0]; dl[1] = sl[1];
        }
        __syncthreads();
        // ---- compute 2 x k16
#pragma unroll
        for (int kk = 0; kk < BK; kk += 16) {
            uint32_t ah[2][4], al[2][4], bh[8][2], bl[8][2];
#pragma unroll
            for (int mi = 0; mi < 2; mi++) {
                uint32_t off = ((m_base + mi * 16 + a_row) * BKP + kk + a_coff) * 2;
                ldsm_x4(ah[mi][0], ah[mi][1], ah[mi][2], ah[mi][3], uAh + off);
                ldsm_x4(al[mi][0], al[mi][1], al[mi][2], al[mi][3], uAl + off);
            }
#pragma unroll
            for (int nj = 0; nj < 4; nj++) {
                uint32_t off = ((n_base + nj * 16 + b_row) * BKP + kk + b_coff) * 2;
                ldsm_x4(bh[2 * nj][0], bh[2 * nj][1], bh[2 * nj + 1][0], bh[2 * nj + 1][1], uBh + off);
                ldsm_x4(bl[2 * nj][0], bl[2 * nj][1], bl[2 * nj + 1][0], bl[2 * nj + 1][1], uBl + off);
            }
#pragma unroll
            for (int mi = 0; mi < 2; mi++)
#pragma unroll
                for (int ni = 0; ni < 8; ni++) {
                    mma_bf16(acc[mi][ni], ah[mi], bh[ni]);
                    mma_bf16(acc[mi][ni], ah[mi], bl[ni]);
                    mma_bf16(acc[mi][ni], al[mi], bh[ni]);
                }
        }
    }

    // ---- epilogue: accumulators -> global (bias + leaky-relu)
    int g = lane >> 2, tg = lane & 3;
#pragma unroll
    for (int mi = 0; mi < 2; mi++) {
        int r0 = bm + m_base + mi * 16 + g;
        int r1 = r0 + 8;
#pragma unroll
        for (int ni = 0; ni < 8; ni++) {
            int c = bn + n_base + ni * 8 + 2 * tg;
            float2 v0 = make_float2(acc[mi][ni][0], acc[mi][ni][1]);
            float2 v1 = make_float2(acc[mi][ni][2], acc[mi][ni][3]);
            if (bias) {
                float bx = bias[c], by = bias[c + 1];
                v0.x += bx; v0.y += by;
                v1.x += bx; v1.y += by;
            }
            if (act) {
                v0.x = LRELU(v0.x); v0.y = LRELU(v0.y);
                v1.x = LRELU(v1.x); v1.y = LRELU(v1.y);
            }
            if (r0 < M) *reinterpret_cast<float2*>(&out[(size_t)r0 * N + c]) = v0;
            if (r1 < M) *reinterpret_cast<float2*>(&out[(size_t)r1 * N + c]) = v1;
        }
    }
}

// ---------------- pooling + logits ----------------
__global__ void k_pool() {
    int g = blockIdx.x;
    int t = threadIdx.x;
    int s0 = g_goff[g], s1 = g_goff[g + 1];
    float acc = 0.f;
    for (int n = s0; n < s1; n++) acc += g_latent[(size_t)n * 256 + t];
    float cnt = (float)(s1 - s0);
    if (cnt < 1.f) cnt = 1.f;
    g_pooled[g * 256 + t] = acc / cnt;
}
__global__ void k_logits(const float* __restrict__ w_lin, const float* __restrict__ b_lin,
                         float* __restrict__ out) {
    int idx = blockIdx.x * blockDim.x + threadIdx.x;
    if (idx >= NG * 7) return;
    int g = idx / 7, o = idx % 7;
    float acc = b_lin[o];
    for (int k = 0; k < 256; k++) acc += g_pooled[g * 256 + k] * w_lin[k * 7 + o];
    out[g * 7 + o] = acc;
}

// ---------------- launch ----------------
extern "C" void kernel_launch(void* const* d_in, const int* in_sizes, int n_in,
                              void* d_out, int out_size) {
    const int*   x       = (const int*)d_in[0];
    const int*   ei      = (const int*)d_in[1];
    const int*   batch   = (const int*)d_in[2];
    const float* emb     = (const float*)d_in[3];
    const float* w1_rel  = (const float*)d_in[4];
    const float* w1_root = (const float*)d_in[5];
    const float* b1      = (const float*)d_in[6];
    const float* w2_rel  = (const float*)d_in[7];
    const float* w2_root = (const float*)d_in[8];
    const float* b2      = (const float*)d_in[9];
    const float* we_rel  = (const float*)d_in[10];
    const float* we_root = (const float*)d_in[11];
    const float* be      = (const float*)d_in[12];
    const float* wd_rel  = (const float*)d_in[13];
    const float* wd_root = (const float*)d_in[14];
    const float* bd      = (const float*)d_in[15];
    const float* w_lin   = (const float*)d_in[16];
    const float* b_lin   = (const float*)d_in[17];

    const int* src = ei;
    const int* dst = ei + NE;

    float* out_f  = (float*)d_out;
    float* logits = out_f;
    float* recon  = out_f + NG * 7;
    float* orig   = out_f + NG * 7 + (size_t)NN * 1024;

    // scratch symbol addresses
    float *a64, *h1, *enc, *a256, *lat, *adec;
    cudaGetSymbolAddress((void**)&a64,  g_aggr64);
    cudaGetSymbolAddress((void**)&h1,   g_h1);
    cudaGetSymbolAddress((void**)&enc,  g_enc);
    cudaGetSymbolAddress((void**)&a256, g_aggr256);
    cudaGetSymbolAddress((void**)&lat,  g_latent);
    cudaGetSymbolAddress((void**)&adec, g_aggdec);
    __nv_bfloat16 *bc2h, *bc2l, *beh, *bel, *bdh, *bdl;
    cudaGetSymbolAddress((void**)&bc2h, g_Bc2h);
    cudaGetSymbolAddress((void**)&bc2l, g_Bc2l);
    cudaGetSymbolAddress((void**)&beh,  g_Beh);
    cudaGetSymbolAddress((void**)&bel,  g_Bel);
    cudaGetSymbolAddress((void**)&bdh,  g_Bdh);
    cudaGetSymbolAddress((void**)&bdl,  g_Bdl);

    // CSR + graph offsets
    k_zero_counts<<<(NN + 255) / 256, 256>>>();
    k_hist_edges<<<(NE + 255) / 256, 256>>>(dst);
    k_hist_nodes<<<(NN + 255) / 256, 256>>>(batch);
    k_scan_nodes<<<1, 1024>>>();
    k_scan_graphs<<<1, NG>>>();
    k_copy_cursor<<<(NN + 255) / 256, 256>>>();
    k_scatter<<<(NE + 255) / 256, 256>>>(src, dst);

    // weight prep (transpose + bf16 hi/lo split, K-major concat layouts)
    k_prep<<<dim3(128 / 32, 1024 / 32), dim3(32, 8)>>>(w2_rel, w2_root, 128, 1024, 64, 0, bc2h, bc2l);
    k_prep<<<dim3(1024 / 32, 512 / 32), dim3(32, 8)>>>(we_rel, we_root, 1024, 512, 256, 1, beh, bel);
    k_prep<<<dim3(512 / 32, 1024 / 32), dim3(32, 8)>>>(wd_rel, wd_root, 512, 1024, 256, 0, bdh, bdl);

    // conv1
    k_conv1<<<NN, 64>>>(x, emb, w1_rel, w1_root, b1);
    k_agg64<<<(NN + 3) / 4, 128>>>();

    int gy = (NN + BM - 1) / BM;  // 391

    // conv2: [aggr64 | h1] @ Bc2 -> orig   (M=50000, N=1024, K=128)
    gemm_tc<<<dim3(1024 / BN, gy), 256>>>(
        a64, 64, h1, 64, 64, bc2h, bc2l, b2, orig, NN, 1024, 128, 1);

    // enc: orig @ [we_rel | we_root] -> g_enc  (N=512, K=1024, raw)
    gemm_tc<<<dim3(512 / BN, gy), 256>>>(
        orig, 1024, nullptr, 0, 1024, beh, bel, nullptr, enc, NN, 512, 1024, 0);
    k_agg256<<<NN, 256>>>(enc, 512, a256);
    k_enc_finish<<<(NN * 256 + 255) / 256, 256>>>(be);

    // dec: [agg(latent) | latent] @ Bd -> recon  (N=1024, K=512)
    k_agg256<<<NN, 256>>>(lat, 256, adec);
    gemm_tc<<<dim3(1024 / BN, gy), 256>>>(
        adec, 256, lat, 256, 256, bdh, bdl, bd, recon, NN, 1024, 512, 1);

    // pooling + logits
    k_pool<<<NG, 256>>>();
    k_logits<<<(NG * 7 + 255) / 256, 256>>>(w_lin, b_lin, logits);
}

// round 12
// speedup vs baseline: 2.1490x; 1.2468x over previous
#include <cuda_runtime.h>
#include <cuda_bf16.h>
#include <cstdint>

#define NN 50000
#define NE 800000
#define NG 256
#define NBLK 49   // ceil(NN/1024)
#define LRELU(v) ((v) >= 0.f ? (v) : 0.01f * (v))

// ---------------- scratch (static device allocations; no cudaMalloc) ----------------
__device__ int   g_deg[NN];
__device__ int   g_off[NN + 1];
__device__ int   g_cursor[NN];
__device__ int   g_perm[NE];
__device__ int   g_btot[NBLK];
__device__ int   g_gcount[NG];
__device__ int   g_goff[NG + 1];
__device__ float g_h1[(size_t)NN * 64];
__device__ float g_enc[(size_t)NN * 512];      // enc GEMM out: cols 0-255 rel-proj, 256-511 root-proj
__device__ float g_aggr256[(size_t)NN * 256];
__device__ float g_latent[(size_t)NN * 256];
__device__ float g_pooled[NG * 256];
// pre-split bf16 A operands (row-major, K-major contiguous)
__device__ __nv_bfloat16 g_Ac2h[(size_t)NN * 128],  g_Ac2l[(size_t)NN * 128];   // [aggr64 | h1]
__device__ __nv_bfloat16 g_Aeh[(size_t)NN * 1024],  g_Ael[(size_t)NN * 1024];   // orig
__device__ __nv_bfloat16 g_Adh[(size_t)NN * 512],   g_Adl[(size_t)NN * 512];    // [adec | latent]
// transposed + bf16-split weights (K-major: [N, Ktot])
__device__ __nv_bfloat16 g_Bc2h[1024 * 128], g_Bc2l[1024 * 128];
__device__ __nv_bfloat16 g_Beh[512 * 1024],  g_Bel[512 * 1024];
__device__ __nv_bfloat16 g_Bdh[1024 * 512],  g_Bdl[1024 * 512];

// ---------------- helpers ----------------
__device__ __forceinline__ uint32_t smem_u32(const void* p) {
    uint32_t a;
    asm("{ .reg .u64 t; cvta.to.shared.u64 t, %1; cvt.u32.u64 %0, t; }" : "=r"(a) : "l"(p));
    return a;
}
__device__ __forceinline__ void ldsm_x4(uint32_t& r0, uint32_t& r1, uint32_t& r2, uint32_t& r3,
                                        uint32_t addr) {
    asm volatile("ldmatrix.sync.aligned.m8n8.x4.shared.b16 {%0,%1,%2,%3}, [%4];"
                 : "=r"(r0), "=r"(r1), "=r"(r2), "=r"(r3) : "r"(addr));
}
__device__ __forceinline__ void mma_bf16(float* c, const uint32_t* a, const uint32_t* b) {
    asm volatile(
        "mma.sync.aligned.m16n8k16.row.col.f32.bf16.bf16.f32 "
        "{%0,%1,%2,%3}, {%4,%5,%6,%7}, {%8,%9}, {%0,%1,%2,%3};"
        : "+f"(c[0]), "+f"(c[1]), "+f"(c[2]), "+f"(c[3])
        : "r"(a[0]), "r"(a[1]), "r"(a[2]), "r"(a[3]), "r"(b[0]), "r"(b[1]));
}
__device__ __forceinline__ void split1(float a, __nv_bfloat16& h, __nv_bfloat16& l) {
    h = __float2bfloat16(a);
    l = __float2bfloat16(a - __bfloat162float(h));
}
__device__ __forceinline__ void cp16(uint32_t dst, const void* src, bool ok) {
    int sz = ok ? 16 : 0;
    asm volatile("cp.async.cg.shared.global [%0], [%1], 16, %2;"
                 :: "r"(dst), "l"(src), "r"(sz) : "memory");
}

// ---------------- CSR construction ----------------
__global__ void k_zero_counts() {
    int i = blockIdx.x * blockDim.x + threadIdx.x;
    if (i < NN) g_deg[i] = 0;
    if (i < NG) g_gcount[i] = 0;
}
__global__ void k_hist_edges(const int* __restrict__ dst) {
    int e = blockIdx.x * blockDim.x + threadIdx.x;
    if (e < NE) atomicAdd(&g_deg[dst[e]], 1);
}
__global__ void k_hist_nodes(const int* __restrict__ batch) {
    int i = blockIdx.x * blockDim.x + threadIdx.x;
    if (i < NN) atomicAdd(&g_gcount[batch[i]], 1);
}
// multi-block scan: partial per-block inclusive scans + block totals
__global__ void k_scan_part() {
    __shared__ int wsum[32];
    int t = threadIdx.x, lane = t & 31, w = t >> 5;
    int idx = blockIdx.x * 1024 + t;
    int v = (idx < NN) ? g_deg[idx] : 0;
    int sc = v;
#pragma unroll
    for (int o = 1; o < 32; o <<= 1) { int u = __shfl_up_sync(~0u, sc, o); if (lane >= o) sc += u; }
    if (lane == 31) wsum[w] = sc;
    __syncthreads();
    if (w == 0) {
        int s = wsum[lane];
#pragma unroll
        for (int o = 1; o < 32; o <<= 1) { int u = __shfl_up_sync(~0u, s, o); if (lane >= o) s += u; }
        wsum[lane] = s;
    }
    __syncthreads();
    int inc = ((w > 0) ? wsum[w - 1] : 0) + sc;
    if (idx < NN) g_off[idx + 1] = inc;
    if (t == 1023) g_btot[blockIdx.x] = inc;
}
__global__ void k_scan_tot() {  // one warp scans NBLK block totals -> exclusive
    int lane = threadIdx.x;
    int a = (lane < NBLK) ? g_btot[lane] : 0;
    int b = (lane + 32 < NBLK) ? g_btot[lane + 32] : 0;
    int sa = a, sb = b;
#pragma unroll
    for (int o = 1; o < 32; o <<= 1) { int u = __shfl_up_sync(~0u, sa, o); if (lane >= o) sa += u; }
    int T = __shfl_sync(~0u, sa, 31);
#pragma unroll
    for (int o = 1; o < 32; o <<= 1) { int u = __shfl_up_sync(~0u, sb, o); if (lane >= o) sb += u; }
    if (lane < NBLK) g_btot[lane] = sa - a;
    if (lane + 32 < NBLK) g_btot[lane + 32] = T + sb - b;
}
__global__ void k_scan_add() {
    int i = blockIdx.x * blockDim.x + threadIdx.x;
    if (i < NN) g_off[i + 1] += g_btot[i >> 10];
    if (i == 0) g_off[0] = 0;
}
__global__ void k_scan_graphs() {
    __shared__ int s[NG];
    int t = threadIdx.x;
    s[t] = g_gcount[t];
    __syncthreads();
    for (int off = 1; off < NG; off <<= 1) {
        int tv = (t >= off) ? s[t - off] : 0;
        __syncthreads();
        s[t] += tv;
        __syncthreads();
    }
    g_goff[t + 1] = s[t];
    if (t == 0) g_goff[0] = 0;
}
__global__ void k_copy_cursor() {
    int i = blockIdx.x * blockDim.x + threadIdx.x;
    if (i < NN) g_cursor[i] = g_off[i];
}
__global__ void k_scatter(const int* __restrict__ src, const int* __restrict__ dst) {
    int e = blockIdx.x * blockDim.x + threadIdx.x;
    if (e < NE) {
        int d = dst[e];
        int p = atomicAdd(&g_cursor[d], 1);
        g_perm[p] = src[e];
    }
}

// ---------------- conv1 (writes fp32 h1 + bf16 hi/lo into Ac2 cols 64..127) ----------------
__global__ void k_conv1(const int* __restrict__ x, const float* __restrict__ emb,
                        const float* __restrict__ w_rel, const float* __restrict__ w_root,
                        const float* __restrict__ b1) {
    int i = blockIdx.x;
    int t = threadIdx.x;  // 64
    __shared__ float embs[30];
    __shared__ float aggr[3];
    if (t < 30) embs[t] = emb[t];
    __syncthreads();
    if (t < 3) {
        float a = 0.f;
        int s0 = g_off[i], s1 = g_off[i + 1];
        for (int e = s0; e < s1; e++) a += embs[x[g_perm[e]] * 3 + t];
        aggr[t] = a;
    }
    __syncthreads();
    int lab = x[i];
    float v = b1[t];
#pragma unroll
    for (int c = 0; c < 3; c++)
        v += aggr[c] * w_rel[c * 64 + t] + embs[lab * 3 + c] * w_root[c * 64 + t];
    float r = LRELU(v);
    g_h1[(size_t)i * 64 + t] = r;
    __nv_bfloat16 h, l;
    split1(r, h, l);
    g_Ac2h[(size_t)i * 128 + 64 + t] = h;
    g_Ac2l[(size_t)i * 128 + 64 + t] = l;
}

// ---------------- aggregations ----------------
__global__ void k_agg64() {  // aggregate h1, write bf16 hi/lo into Ac2 cols 0..63
    int w = threadIdx.x >> 5, lane = threadIdx.x & 31;
    int i = blockIdx.x * 4 + w;
    if (i >= NN) return;
    const float2* h = reinterpret_cast<const float2*>(g_h1);
    float2 acc = make_float2(0.f, 0.f);
    int s0 = g_off[i], s1 = g_off[i + 1];
    for (int e = s0; e < s1; e++) {
        float2 v = h[(size_t)g_perm[e] * 32 + lane];
        acc.x += v.x;
        acc.y += v.y;
    }
    __nv_bfloat16 hx, lx, hy, ly;
    split1(acc.x, hx, lx);
    split1(acc.y, hy, ly);
    reinterpret_cast<__nv_bfloat162*>(g_Ac2h)[(size_t)i * 64 + lane] = __halves2bfloat162(hx, hy);
    reinterpret_cast<__nv_bfloat162*>(g_Ac2l)[(size_t)i * 64 + lane] = __halves2bfloat162(lx, ly);
}
// 256-wide aggregation with optional fp32 and/or bf16-split outputs
__global__ void k_agg256(const float* __restrict__ in, int ldin, float* __restrict__ f32out,
                         __nv_bfloat16* __restrict__ oh, __nv_bfloat16* __restrict__ ol,
                         int ldo, int coff) {
    int i = blockIdx.x;
    int t = threadIdx.x;  // 256
    int s0 = g_off[i], s1 = g_off[i + 1];
    float acc = 0.f;
    for (int e = s0; e < s1; e++) acc += in[(size_t)g_perm[e] * ldin + t];
    if (f32out) f32out[(size_t)i * 256 + t] = acc;
    if (oh) {
        __nv_bfloat16 h, l;
        split1(acc, h, l);
        oh[(size_t)i * ldo + coff + t] = h;
        ol[(size_t)i * ldo + coff + t] = l;
    }
}
__global__ void k_enc_finish(const float* __restrict__ be) {
    int idx = blockIdx.x * blockDim.x + threadIdx.x;
    if (idx >= NN * 256) return;
    int i = idx >> 8, c = idx & 255;
    float v = g_enc[(size_t)i * 512 + 256 + c] + g_aggr256[idx] + be[c];
    float r = LRELU(v);
    g_latent[idx] = r;
    __nv_bfloat16 h, l;
    split1(r, h, l);
    g_Adh[(size_t)i * 512 + 256 + c] = h;
    g_Adl[(size_t)i * 512 + 256 + c] = l;
}

// ---------------- weight transpose + bf16 split ----------------
__global__ void k_prep(const float* __restrict__ s1, const float* __restrict__ s2,
                       int Ktot, int Ntot, int split, int mode,
                       __nv_bfloat16* __restrict__ dh, __nv_bfloat16* __restrict__ dl) {
    __shared__ float tile[32][33];
    int k0 = blockIdx.x * 32, n0 = blockIdx.y * 32;
    int tx = threadIdx.x, ty = threadIdx.y;  // (32, 8)
#pragma unroll
    for (int r = 0; r < 32; r += 8) {
        int k = k0 + ty + r, n = n0 + tx;
        float v;
        if (mode == 0)
            v = (k < split) ? s1[(size_t)k * Ntot + n] : s2[(size_t)(k - split) * Ntot + n];
        else
            v = (n < split) ? s1[(size_t)k * split + n] : s2[(size_t)k * (Ntot - split) + (n - split)];
        tile[ty + r][tx] = v;
    }
    __syncthreads();
#pragma unroll
    for (int r = 0; r < 32; r += 8) {
        int n = n0 + ty + r, k = k0 + tx;
        float v = tile[tx][ty + r];
        __nv_bfloat16 h, l;
        split1(v, h, l);
        dh[(size_t)n * Ktot + k] = h;
        dl[(size_t)n * Ktot + k] = l;
    }
}

// ---------------- HMMA bf16x3 GEMM, cp.async double-buffered ----------------
// out[M,N] = act( A[M,Ktot] @ B^T + bias ); A,B pre-split bf16 hi/lo.
// Block 128x128, BK=32, 256 thr, warps 4(m) x 2(n), warp tile 32x64.
#define BM 128
#define BN 128
#define BK 32
#define BKP 40                       // padded K stride (elements) -> 80B rows
#define OFF_AH 0
#define OFF_AL (BM * BKP * 2)        // 10240
#define OFF_BH (2 * BM * BKP * 2)    // 20480
#define OFF_BL (3 * BM * BKP * 2)    // 30720
#define STAGE  (4 * BM * BKP * 2)    // 40960
#define GEMM_SMEM (2 * STAGE)        // 81920

__global__ __launch_bounds__(256) void gemm_tc(
    const __nv_bfloat16* __restrict__ Ah, const __nv_bfloat16* __restrict__ Al, int lda,
    const __nv_bfloat16* __restrict__ Bh, const __nv_bfloat16* __restrict__ Bl,
    const float* __restrict__ bias, float* __restrict__ out,
    __nv_bfloat16* __restrict__ outh, __nv_bfloat16* __restrict__ outl, int ldo,
    int M, int N, int Ktot, int act) {
    extern __shared__ char smem[];
    uint32_t uS = smem_u32(smem);
    int tid = threadIdx.x, lane = tid & 31, wid = tid >> 5;
    int wm = wid & 3, wn = wid >> 2;
    int m_base = wm * 32, n_base = wn * 64;
    int bm = blockIdx.y * BM, bn = blockIdx.x * BN;

    float acc[2][8][4];
#pragma unroll
    for (int i = 0; i < 2; i++)
#pragma unroll
        for (int j = 0; j < 8; j++)
#pragma unroll
            for (int q = 0; q < 4; q++) acc[i][j][q] = 0.f;

    // staging map: 2 threads per row, 16 cols (32B = 2x16B chunks) each
    int r = tid >> 1, c16 = (tid & 1) * 16;
    int gm = bm + r;
    bool okA = (gm < M);
    const char* pAh = (const char*)(Ah + (size_t)(okA ? gm : 0) * lda + c16);
    const char* pAl = (const char*)(Al + (size_t)(okA ? gm : 0) * lda + c16);
    const char* pBh = (const char*)(Bh + (size_t)(bn + r) * Ktot + c16);
    const char* pBl = (const char*)(Bl + (size_t)(bn + r) * Ktot + c16);
    uint32_t sdst = (uint32_t)((r * BKP + c16) * 2);

    auto issue = [&](int s) {
        uint32_t sb = uS + (uint32_t)(s & 1) * STAGE + sdst;
        size_t ko = (size_t)s * BK * 2;  // bytes
        cp16(sb + OFF_AH,      pAh + ko,      okA);
        cp16(sb + OFF_AH + 16, pAh + ko + 16, okA);
        cp16(sb + OFF_AL,      pAl + ko,      okA);
        cp16(sb + OFF_AL + 16, pAl + ko + 16, okA);
        cp16(sb + OFF_BH,      pBh + ko,      true);
        cp16(sb + OFF_BH + 16, pBh + ko + 16, true);
        cp16(sb + OFF_BL,      pBl + ko,      true);
        cp16(sb + OFF_BL + 16, pBl + ko + 16, true);
        asm volatile("cp.async.commit_group;" ::: "memory");
    };

    // ldmatrix lane address components
    int a_row = (lane & 15);
    int a_coff = (lane >> 4) * 8;
    int b_row = ((lane >> 4) << 3) + (lane & 7);
    int b_coff = ((lane >> 3) & 1) * 8;

    int nst = Ktot / BK;
    issue(0);
    for (int s = 0; s < nst; s++) {
        if (s + 1 < nst) {
            issue(s + 1);
            asm volatile("cp.async.wait_group 1;" ::: "memory");
        } else {
            asm volatile("cp.async.wait_group 0;" ::: "memory");
        }
        __syncthreads();
        uint32_t sb = uS + (uint32_t)(s & 1) * STAGE;
#pragma unroll
        for (int kk = 0; kk < BK; kk += 16) {
            uint32_t ah[2][4], al[2][4], bh[8][2], bl[8][2];
#pragma unroll
            for (int mi = 0; mi < 2; mi++) {
                uint32_t off = (uint32_t)(((m_base + mi * 16 + a_row) * BKP + kk + a_coff) * 2);
                ldsm_x4(ah[mi][0], ah[mi][1], ah[mi][2], ah[mi][3], sb + OFF_AH + off);
                ldsm_x4(al[mi][0], al[mi][1], al[mi][2], al[mi][3], sb + OFF_AL + off);
            }
#pragma unroll
            for (int nj = 0; nj < 4; nj++) {
                uint32_t off = (uint32_t)(((n_base + nj * 16 + b_row) * BKP + kk + b_coff) * 2);
                ldsm_x4(bh[2 * nj][0], bh[2 * nj][1], bh[2 * nj + 1][0], bh[2 * nj + 1][1], sb + OFF_BH + off);
                ldsm_x4(bl[2 * nj][0], bl[2 * nj][1], bl[2 * nj + 1][0], bl[2 * nj + 1][1], sb + OFF_BL + off);
            }
#pragma unroll
            for (int mi = 0; mi < 2; mi++)
#pragma unroll
                for (int ni = 0; ni < 8; ni++) {
                    mma_bf16(acc[mi][ni], ah[mi], bh[ni]);
                    mma_bf16(acc[mi][ni], ah[mi], bl[ni]);
                    mma_bf16(acc[mi][ni], al[mi], bh[ni]);
                }
        }
        __syncthreads();
    }

    // ---- epilogue: bias + leaky-relu; fp32 store + optional bf16 hi/lo split store
    int gq = lane >> 2, tg = lane & 3;
#pragma unroll
    for (int mi = 0; mi < 2; mi++) {
        int r0 = bm + m_base + mi * 16 + gq;
        int r1 = r0 + 8;
#pragma unroll
        for (int ni = 0; ni < 8; ni++) {
            int c = bn + n_base + ni * 8 + 2 * tg;
            float2 v0 = make_float2(acc[mi][ni][0], acc[mi][ni][1]);
            float2 v1 = make_float2(acc[mi][ni][2], acc[mi][ni][3]);
            if (bias) {
                float bx = bias[c], by = bias[c + 1];
                v0.x += bx; v0.y += by;
                v1.x += bx; v1.y += by;
            }
            if (act) {
                v0.x = LRELU(v0.x); v0.y = LRELU(v0.y);
                v1.x = LRELU(v1.x); v1.y = LRELU(v1.y);
            }
            if (r0 < M) {
                *reinterpret_cast<float2*>(&out[(size_t)r0 * N + c]) = v0;
                if (outh) {
                    __nv_bfloat16 hx, lx, hy, ly;
                    split1(v0.x, hx, lx); split1(v0.y, hy, ly);
                    *reinterpret_cast<__nv_bfloat162*>(&outh[(size_t)r0 * ldo + c]) = __halves2bfloat162(hx, hy);
                    *reinterpret_cast<__nv_bfloat162*>(&outl[(size_t)r0 * ldo + c]) = __halves2bfloat162(lx, ly);
                }
            }
            if (r1 < M) {
                *reinterpret_cast<float2*>(&out[(size_t)r1 * N + c]) = v1;
                if (outh) {
                    __nv_bfloat16 hx, lx, hy, ly;
                    split1(v1.x, hx, lx); split1(v1.y, hy, ly);
                    *reinterpret_cast<__nv_bfloat162*>(&outh[(size_t)r1 * ldo + c]) = __halves2bfloat162(hx, hy);
                    *reinterpret_cast<__nv_bfloat162*>(&outl[(size_t)r1 * ldo + c]) = __halves2bfloat162(lx, ly);
                }
            }
        }
    }
}

// ---------------- pooling + logits ----------------
__global__ void k_pool() {
    int g = blockIdx.x;
    int t = threadIdx.x;
    int s0 = g_goff[g], s1 = g_goff[g + 1];
    float acc = 0.f;
    for (int n = s0; n < s1; n++) acc += g_latent[(size_t)n * 256 + t];
    float cnt = (float)(s1 - s0);
    if (cnt < 1.f) cnt = 1.f;
    g_pooled[g * 256 + t] = acc / cnt;
}
__global__ void k_logits(const float* __restrict__ w_lin, const float* __restrict__ b_lin,
                         float* __restrict__ out) {
    int idx = blockIdx.x * blockDim.x + threadIdx.x;
    if (idx >= NG * 7) return;
    int g = idx / 7, o = idx % 7;
    float acc = b_lin[o];
    for (int k = 0; k < 256; k++) acc += g_pooled[g * 256 + k] * w_lin[k * 7 + o];
    out[g * 7 + o] = acc;
}

// ---------------- launch ----------------
extern "C" void kernel_launch(void* const* d_in, const int* in_sizes, int n_in,
                              void* d_out, int out_size) {
    const int*   x       = (const int*)d_in[0];
    const int*   ei      = (const int*)d_in[1];
    const int*   batch   = (const int*)d_in[2];
    const float* emb     = (const float*)d_in[3];
    const float* w1_rel  = (const float*)d_in[4];
    const float* w1_root = (const float*)d_in[5];
    const float* b1      = (const float*)d_in[6];
    const float* w2_rel  = (const float*)d_in[7];
    const float* w2_root = (const float*)d_in[8];
    const float* b2      = (const float*)d_in[9];
    const float* we_rel  = (const float*)d_in[10];
    const float* we_root = (const float*)d_in[11];
    const float* be      = (const float*)d_in[12];
    const float* wd_rel  = (const float*)d_in[13];
    const float* wd_root = (const float*)d_in[14];
    const float* bd      = (const float*)d_in[15];
    const float* w_lin   = (const float*)d_in[16];
    const float* b_lin   = (const float*)d_in[17];

    const int* src = ei;
    const int* dst = ei + NE;

    float* out_f  = (float*)d_out;
    float* logits = out_f;
    float* recon  = out_f + NG * 7;
    float* orig   = out_f + NG * 7 + (size_t)NN * 1024;

    cudaFuncSetAttribute(gemm_tc, cudaFuncAttributeMaxDynamicSharedMemorySize, GEMM_SMEM);

    // scratch symbol addresses
    float *enc, *a256, *lat;
    cudaGetSymbolAddress((void**)&enc,  g_enc);
    cudaGetSymbolAddress((void**)&a256, g_aggr256);
    cudaGetSymbolAddress((void**)&lat,  g_latent);
    __nv_bfloat16 *ac2h, *ac2l, *aeh, *ael, *adh, *adl;
    cudaGetSymbolAddress((void**)&ac2h, g_Ac2h);
    cudaGetSymbolAddress((void**)&ac2l, g_Ac2l);
    cudaGetSymbolAddress((void**)&aeh,  g_Aeh);
    cudaGetSymbolAddress((void**)&ael,  g_Ael);
    cudaGetSymbolAddress((void**)&adh,  g_Adh);
    cudaGetSymbolAddress((void**)&adl,  g_Adl);
    __nv_bfloat16 *bc2h, *bc2l, *beh, *bel, *bdh, *bdl;
    cudaGetSymbolAddress((void**)&bc2h, g_Bc2h);
    cudaGetSymbolAddress((void**)&bc2l, g_Bc2l);
    cudaGetSymbolAddress((void**)&beh,  g_Beh);
    cudaGetSymbolAddress((void**)&bel,  g_Bel);
    cudaGetSymbolAddress((void**)&bdh,  g_Bdh);
    cudaGetSymbolAddress((void**)&bdl,  g_Bdl);

    // CSR + graph offsets
    k_zero_counts<<<(NN + 255) / 256, 256>>>();
    k_hist_edges<<<(NE + 255) / 256, 256>>>(dst);
    k_hist_nodes<<<(NN + 255) / 256, 256>>>(batch);
    k_scan_part<<<NBLK, 1024>>>();
    k_scan_tot<<<1, 32>>>();
    k_scan_add<<<(NN + 255) / 256, 256>>>();
    k_scan_graphs<<<1, NG>>>();
    k_copy_cursor<<<(NN + 255) / 256, 256>>>();
    k_scatter<<<(NE + 255) / 256, 256>>>(src, dst);

    // weight prep (transpose + bf16 hi/lo split, K-major concat layouts)
    k_prep<<<dim3(128 / 32, 1024 / 32), dim3(32, 8)>>>(w2_rel, w2_root, 128, 1024, 64, 0, bc2h, bc2l);
    k_prep<<<dim3(1024 / 32, 512 / 32), dim3(32, 8)>>>(we_rel, we_root, 1024, 512, 256, 1, beh, bel);
    k_prep<<<dim3(512 / 32, 1024 / 32), dim3(32, 8)>>>(wd_rel, wd_root, 512, 1024, 256, 0, bdh, bdl);

    // conv1
    k_conv1<<<NN, 64>>>(x, emb, w1_rel, w1_root, b1);
    k_agg64<<<(NN + 3) / 4, 128>>>();

    int gy = (NN + BM - 1) / BM;  // 391

    // conv2: [aggr64 | h1] @ Bc2 -> orig (fp32 out) + bf16 split for enc A
    gemm_tc<<<dim3(1024 / BN, gy), 256, GEMM_SMEM>>>(
        ac2h, ac2l, 128, bc2h, bc2l, b2, orig, aeh, ael, 1024, NN, 1024, 128, 1);

    // enc: orig @ [we_rel | we_root] -> g_enc (raw fp32)
    gemm_tc<<<dim3(512 / BN, gy), 256, GEMM_SMEM>>>(
        aeh, ael, 1024, beh, bel, nullptr, enc, nullptr, nullptr, 0, NN, 512, 1024, 0);
    k_agg256<<<NN, 256>>>(enc, 512, a256, nullptr, nullptr, 0, 0);
    k_enc_finish<<<(NN * 256 + 255) / 256, 256>>>(be);

    // dec: aggregate latent -> bf16 split into Ad cols 0..255, then GEMM
    k_agg256<<<NN, 256>>>(lat, 256, nullptr, adh, adl, 512, 0);
    gemm_tc<<<dim3(1024 / BN, gy), 256, GEMM_SMEM>>>(
        adh, adl, 512, bdh, bdl, bd, recon, nullptr, nullptr, 0, NN, 1024, 512, 1);

    // pooling + logits
    k_pool<<<NG, 256>>>();
    k_logits<<<(NG * 7 + 255) / 256, 256>>>(w_lin, b_lin, logits);
}

// round 15
// speedup vs baseline: 2.6888x; 1.2512x over previous
#include <cuda_runtime.h>
#include <cuda_fp16.h>
#include <cstdint>

#define NN 50000
#define NE 800000
#define NG 256
#define NBLK 49   // ceil(NN/1024)
#define LRELU(v) ((v) >= 0.f ? (v) : 0.01f * (v))

// ---------------- scratch (static device allocations; no cudaMalloc) ----------------
__device__ int   g_deg[NN];
__device__ int   g_off[NN + 1];
__device__ int   g_cursor[NN];
__device__ int   g_perm[NE];
__device__ int   g_btot[NBLK];
__device__ int   g_gcount[NG];
__device__ int   g_goff[NG + 1];
__device__ float g_h1[(size_t)NN * 64];
__device__ float g_enc[(size_t)NN * 512];      // enc GEMM out: cols 0-255 rel-proj, 256-511 root-proj
__device__ float g_aggr256[(size_t)NN * 256];
__device__ float g_latent[(size_t)NN * 256];
__device__ float g_pooled[NG * 256];
// fp16 A operands (row-major, K contiguous)
__device__ __half g_Ac2[(size_t)NN * 128];     // [aggr64 | h1]
__device__ __half g_Ae[(size_t)NN * 1024];     // orig
__device__ __half g_Ad[(size_t)NN * 512];      // [adec | latent]
// transposed + fp16-split weights (K-major: [N, Ktot])
__device__ __half g_Bc2h[1024 * 128], g_Bc2l[1024 * 128];
__device__ __half g_Beh[512 * 1024],  g_Bel[512 * 1024];
__device__ __half g_Bdh[1024 * 512],  g_Bdl[1024 * 512];

// ---------------- helpers ----------------
__device__ __forceinline__ uint32_t smem_u32(const void* p) {
    uint32_t a;
    asm("{ .reg .u64 t; cvta.to.shared.u64 t, %1; cvt.u32.u64 %0, t; }" : "=r"(a) : "l"(p));
    return a;
}
__device__ __forceinline__ void ldsm_x4(uint32_t& r0, uint32_t& r1, uint32_t& r2, uint32_t& r3,
                                        uint32_t addr) {
    asm volatile("ldmatrix.sync.aligned.m8n8.x4.shared.b16 {%0,%1,%2,%3}, [%4];"
                 : "=r"(r0), "=r"(r1), "=r"(r2), "=r"(r3) : "r"(addr));
}
__device__ __forceinline__ void mma_f16(float* c, const uint32_t* a, const uint32_t* b) {
    asm volatile(
        "mma.sync.aligned.m16n8k16.row.col.f32.f16.f16.f32 "
        "{%0,%1,%2,%3}, {%4,%5,%6,%7}, {%8,%9}, {%0,%1,%2,%3};"
        : "+f"(c[0]), "+f"(c[1]), "+f"(c[2]), "+f"(c[3])
        : "r"(a[0]), "r"(a[1]), "r"(a[2]), "r"(a[3]), "r"(b[0]), "r"(b[1]));
}
__device__ __forceinline__ void splith(float a, __half& h, __half& l) {
    h = __float2half_rn(a);
    l = __float2half_rn(a - __half2float(h));
}
__device__ __forceinline__ void cp16(uint32_t dst, const void* src, bool ok) {
    int sz = ok ? 16 : 0;
    asm volatile("cp.async.cg.shared.global [%0], [%1], 16, %2;"
                 :: "r"(dst), "l"(src), "r"(sz) : "memory");
}

// ---------------- CSR construction ----------------
__global__ void k_zero_counts() {
    int i = blockIdx.x * blockDim.x + threadIdx.x;
    if (i < NN) g_deg[i] = 0;
    if (i < NG) g_gcount[i] = 0;
}
__global__ void k_hist_edges(const int* __restrict__ dst) {
    int e = blockIdx.x * blockDim.x + threadIdx.x;
    if (e < NE) atomicAdd(&g_deg[dst[e]], 1);
}
__global__ void k_hist_nodes(const int* __restrict__ batch) {
    int i = blockIdx.x * blockDim.x + threadIdx.x;
    if (i < NN) atomicAdd(&g_gcount[batch[i]], 1);
}
// multi-block scan: partial per-block inclusive scans + block totals
__global__ void k_scan_part() {
    __shared__ int wsum[32];
    int t = threadIdx.x, lane = t & 31, w = t >> 5;
    int idx = blockIdx.x * 1024 + t;
    int v = (idx < NN) ? g_deg[idx] : 0;
    int sc = v;
#pragma unroll
    for (int o = 1; o < 32; o <<= 1) { int u = __shfl_up_sync(~0u, sc, o); if (lane >= o) sc += u; }
    if (lane == 31) wsum[w] = sc;
    __syncthreads();
    if (w == 0) {
        int s = wsum[lane];
#pragma unroll
        for (int o = 1; o < 32; o <<= 1) { int u = __shfl_up_sync(~0u, s, o); if (lane >= o) s += u; }
        wsum[lane] = s;
    }
    __syncthreads();
    int inc = ((w > 0) ? wsum[w - 1] : 0) + sc;
    if (idx < NN) g_off[idx + 1] = inc;
    if (t == 1023) g_btot[blockIdx.x] = inc;
}
__global__ void k_scan_tot() {  // one warp scans NBLK block totals -> exclusive
    int lane = threadIdx.x;
    int a = (lane < NBLK) ? g_btot[lane] : 0;
    int b = (lane + 32 < NBLK) ? g_btot[lane + 32] : 0;
    int sa = a, sb = b;
#pragma unroll
    for (int o = 1; o < 32; o <<= 1) { int u = __shfl_up_sync(~0u, sa, o); if (lane >= o) sa += u; }
    int T = __shfl_sync(~0u, sa, 31);
#pragma unroll
    for (int o = 1; o < 32; o <<= 1) { int u = __shfl_up_sync(~0u, sb, o); if (lane >= o) sb += u; }
    if (lane < NBLK) g_btot[lane] = sa - a;
    if (lane + 32 < NBLK) g_btot[lane + 32] = T + sb - b;
}
__global__ void k_scan_add() {
    int i = blockIdx.x * blockDim.x + threadIdx.x;
    if (i < NN) g_off[i + 1] += g_btot[i >> 10];
    if (i == 0) g_off[0] = 0;
}
__global__ void k_scan_graphs() {
    __shared__ int s[NG];
    int t = threadIdx.x;
    s[t] = g_gcount[t];
    __syncthreads();
    for (int off = 1; off < NG; off <<= 1) {
        int tv = (t >= off) ? s[t - off] : 0;
        __syncthreads();
        s[t] += tv;
        __syncthreads();
    }
    g_goff[t + 1] = s[t];
    if (t == 0) g_goff[0] = 0;
}
__global__ void k_copy_cursor() {
    int i = blockIdx.x * blockDim.x + threadIdx.x;
    if (i < NN) g_cursor[i] = g_off[i];
}
__global__ void k_scatter(const int* __restrict__ src, const int* __restrict__ dst) {
    int e = blockIdx.x * blockDim.x + threadIdx.x;
    if (e < NE) {
        int d = dst[e];
        int p = atomicAdd(&g_cursor[d], 1);
        g_perm[p] = src[e];
    }
}

// ---------------- conv1: warp per node, lanes parallel over edges ----------------
__global__ void k_conv1(const int* __restrict__ x, const float* __restrict__ emb,
                        const float* __restrict__ w_rel, const float* __restrict__ w_root,
                        const float* __restrict__ b1) {
    __shared__ float embs[32];
    int t = threadIdx.x;  // 128
    if (t < 30) embs[t] = emb[t];
    __syncthreads();
    int w = t >> 5, lane = t & 31;
    int i = blockIdx.x * 4 + w;
    if (i >= NN) return;
    int s0 = g_off[i], s1 = g_off[i + 1];
    float a0 = 0.f, a1 = 0.f, a2 = 0.f;
    for (int e = s0 + lane; e < s1; e += 32) {
        int lab = x[g_perm[e]] * 3;
        a0 += embs[lab];
        a1 += embs[lab + 1];
        a2 += embs[lab + 2];
    }
#pragma unroll
    for (int o = 16; o; o >>= 1) {
        a0 += __shfl_down_sync(~0u, a0, o);
        a1 += __shfl_down_sync(~0u, a1, o);
        a2 += __shfl_down_sync(~0u, a2, o);
    }
    a0 = __shfl_sync(~0u, a0, 0);
    a1 = __shfl_sync(~0u, a1, 0);
    a2 = __shfl_sync(~0u, a2, 0);
    int lab = x[i] * 3;
    float e0 = embs[lab], e1 = embs[lab + 1], e2 = embs[lab + 2];
#pragma unroll
    for (int rep = 0; rep < 2; rep++) {
        int c = lane + rep * 32;
        float v = b1[c] + a0 * w_rel[c] + a1 * w_rel[64 + c] + a2 * w_rel[128 + c]
                        + e0 * w_root[c] + e1 * w_root[64 + c] + e2 * w_root[128 + c];
        float r = LRELU(v);
        g_h1[(size_t)i * 64 + c] = r;
        g_Ac2[(size_t)i * 128 + 64 + c] = __float2half_rn(r);
    }
}

// ---------------- aggregations ----------------
__global__ void k_agg64() {  // aggregate h1 (fp32), write fp16 into Ac2 cols 0..63
    int w = threadIdx.x >> 5, lane = threadIdx.x & 31;
    int i = blockIdx.x * 4 + w;
    if (i >= NN) return;
    const float2* h = reinterpret_cast<const float2*>(g_h1);
    float2 acc = make_float2(0.f, 0.f);
    int s0 = g_off[i], s1 = g_off[i + 1];
    for (int e = s0; e < s1; e++) {
        float2 v = h[(size_t)g_perm[e] * 32 + lane];
        acc.x += v.x;
        acc.y += v.y;
    }
    reinterpret_cast<__half2*>(g_Ac2)[(size_t)i * 64 + lane] =
        __floats2half2_rn(acc.x, acc.y);
}
// 256-wide aggregation: optional fp32 out, optional fp16 out
__global__ void k_agg256(const float* __restrict__ in, int ldin, float* __restrict__ f32out,
                         __half* __restrict__ oh, int ldo, int coff) {
    int i = blockIdx.x;
    int t = threadIdx.x;  // 256
    int s0 = g_off[i], s1 = g_off[i + 1];
    float acc = 0.f;
    for (int e = s0; e < s1; e++) acc += in[(size_t)g_perm[e] * ldin + t];
    if (f32out) f32out[(size_t)i * 256 + t] = acc;
    if (oh) oh[(size_t)i * ldo + coff + t] = __float2half_rn(acc);
}
__global__ void k_enc_finish(const float* __restrict__ be) {
    int idx = blockIdx.x * blockDim.x + threadIdx.x;
    if (idx >= NN * 256) return;
    int i = idx >> 8, c = idx & 255;
    float v = g_enc[(size_t)i * 512 + 256 + c] + g_aggr256[idx] + be[c];
    float r = LRELU(v);
    g_latent[idx] = r;
    g_Ad[(size_t)i * 512 + 256 + c] = __float2half_rn(r);
}

// ---------------- weight transpose + fp16 split ----------------
__global__ void k_prep(const float* __restrict__ s1, const float* __restrict__ s2,
                       int Ktot, int Ntot, int split, int mode,
                       __half* __restrict__ dh, __half* __restrict__ dl) {
    __shared__ float tile[32][33];
    int k0 = blockIdx.x * 32, n0 = blockIdx.y * 32;
    int tx = threadIdx.x, ty = threadIdx.y;  // (32, 8)
#pragma unroll
    for (int r = 0; r < 32; r += 8) {
        int k = k0 + ty + r, n = n0 + tx;
        float v;
        if (mode == 0)
            v = (k < split) ? s1[(size_t)k * Ntot + n] : s2[(size_t)(k - split) * Ntot + n];
        else
            v = (n < split) ? s1[(size_t)k * split + n] : s2[(size_t)k * (Ntot - split) + (n - split)];
        tile[ty + r][tx] = v;
    }
    __syncthreads();
#pragma unroll
    for (int r = 0; r < 32; r += 8) {
        int n = n0 + ty + r, k = k0 + tx;
        float v = tile[tx][ty + r];
        __half h, l;
        splith(v, h, l);
        dh[(size_t)n * Ktot + k] = h;
        dl[(size_t)n * Ktot + k] = l;
    }
}

// ---------------- HMMA fp16x2 GEMM, cp.async double-buffered ----------------
// out[M,N] = act( A[M,Ktot] @ (Bh+Bl)^T + bias ); A single fp16, B split hi/lo.
// Block 128x128, BK=32, 256 thr, warps 4(m) x 2(n), warp tile 32x64.
#define BM 128
#define BN 128
#define BK 32
#define BKP 40                       // padded K stride (elements) -> 80B rows
#define OFF_A  0
#define OFF_BH (BM * BKP * 2)        // 10240
#define OFF_BL (2 * BM * BKP * 2)    // 20480
#define STAGE  (3 * BM * BKP * 2)    // 30720
#define GEMM_SMEM (2 * STAGE)        // 61440

__global__ __launch_bounds__(256) void gemm_tc(
    const __half* __restrict__ A, int lda,
    const __half* __restrict__ Bh, const __half* __restrict__ Bl,
    const float* __restrict__ bias, float* __restrict__ out,
    __half* __restrict__ outh, int ldo,
    int M, int N, int Ktot, int act) {
    extern __shared__ char smem[];
    uint32_t uS = smem_u32(smem);
    int tid = threadIdx.x, lane = tid & 31, wid = tid >> 5;
    int wm = wid & 3, wn = wid >> 2;
    int m_base = wm * 32, n_base = wn * 64;
    int bm = blockIdx.y * BM, bn = blockIdx.x * BN;

    float acc[2][8][4];
#pragma unroll
    for (int i = 0; i < 2; i++)
#pragma unroll
        for (int j = 0; j < 8; j++)
#pragma unroll
            for (int q = 0; q < 4; q++) acc[i][j][q] = 0.f;

    // staging map: 2 threads per row, 16 cols (32B = 2x16B chunks) each
    int r = tid >> 1, c16 = (tid & 1) * 16;
    int gm = bm + r;
    bool okA = (gm < M);
    const char* pA  = (const char*)(A + (size_t)(okA ? gm : 0) * lda + c16);
    const char* pBh = (const char*)(Bh + (size_t)(bn + r) * Ktot + c16);
    const char* pBl = (const char*)(Bl + (size_t)(bn + r) * Ktot + c16);
    uint32_t sdst = (uint32_t)((r * BKP + c16) * 2);

    auto issue = [&](int s) {
        uint32_t sb = uS + (uint32_t)(s & 1) * STAGE + sdst;
        size_t ko = (size_t)s * BK * 2;  // bytes
        cp16(sb + OFF_A,       pA + ko,       okA);
        cp16(sb + OFF_A + 16,  pA + ko + 16,  okA);
        cp16(sb + OFF_BH,      pBh + ko,      true);
        cp16(sb + OFF_BH + 16, pBh + ko + 16, true);
        cp16(sb + OFF_BL,      pBl + ko,      true);
        cp16(sb + OFF_BL + 16, pBl + ko + 16, true);
        asm volatile("cp.async.commit_group;" ::: "memory");
    };

    // ldmatrix lane address components
    int a_row = (lane & 15);
    int a_coff = (lane >> 4) * 8;
    int b_row = ((lane >> 4) << 3) + (lane & 7);
    int b_coff = ((lane >> 3) & 1) * 8;

    int nst = Ktot / BK;
    issue(0);
    for (int s = 0; s < nst; s++) {
        if (s + 1 < nst) {
            issue(s + 1);
            asm volatile("cp.async.wait_group 1;" ::: "memory");
        } else {
            asm volatile("cp.async.wait_group 0;" ::: "memory");
        }
        __syncthreads();
        uint32_t sb = uS + (uint32_t)(s & 1) * STAGE;
#pragma unroll
        for (int kk = 0; kk < BK; kk += 16) {
            uint32_t a[2][4], bh[8][2], bl[8][2];
#pragma unroll
            for (int mi = 0; mi < 2; mi++) {
                uint32_t off = (uint32_t)(((m_base + mi * 16 + a_row) * BKP + kk + a_coff) * 2);
                ldsm_x4(a[mi][0], a[mi][1], a[mi][2], a[mi][3], sb + OFF_A + off);
            }
#pragma unroll
            for (int nj = 0; nj < 4; nj++) {
                uint32_t off = (uint32_t)(((n_base + nj * 16 + b_row) * BKP + kk + b_coff) * 2);
                ldsm_x4(bh[2 * nj][0], bh[2 * nj][1], bh[2 * nj + 1][0], bh[2 * nj + 1][1], sb + OFF_BH + off);
                ldsm_x4(bl[2 * nj][0], bl[2 * nj][1], bl[2 * nj + 1][0], bl[2 * nj + 1][1], sb + OFF_BL + off);
            }
#pragma unroll
            for (int mi = 0; mi < 2; mi++)
#pragma unroll
                for (int ni = 0; ni < 8; ni++) {
                    mma_f16(acc[mi][ni], a[mi], bh[ni]);
                    mma_f16(acc[mi][ni], a[mi], bl[ni]);
                }
        }
        __syncthreads();
    }

    // ---- epilogue: bias + leaky-relu; fp32 store + optional fp16 store
    int gq = lane >> 2, tg = lane & 3;
#pragma unroll
    for (int mi = 0; mi < 2; mi++) {
        int r0 = bm + m_base + mi * 16 + gq;
        int r1 = r0 + 8;
#pragma unroll
        for (int ni = 0; ni < 8; ni++) {
            int c = bn + n_base + ni * 8 + 2 * tg;
            float2 v0 = make_float2(acc[mi][ni][0], acc[mi][ni][1]);
            float2 v1 = make_float2(acc[mi][ni][2], acc[mi][ni][3]);
            if (bias) {
                float bx = bias[c], by = bias[c + 1];
                v0.x += bx; v0.y += by;
                v1.x += bx; v1.y += by;
            }
            if (act) {
                v0.x = LRELU(v0.x); v0.y = LRELU(v0.y);
                v1.x = LRELU(v1.x); v1.y = LRELU(v1.y);
            }
            if (r0 < M) {
                *reinterpret_cast<float2*>(&out[(size_t)r0 * N + c]) = v0;
                if (outh)
                    *reinterpret_cast<__half2*>(&outh[(size_t)r0 * ldo + c]) =
                        __floats2half2_rn(v0.x, v0.y);
            }
            if (r1 < M) {
                *reinterpret_cast<float2*>(&out[(size_t)r1 * N + c]) = v1;
                if (outh)
                    *reinterpret_cast<__half2*>(&outh[(size_t)r1 * ldo + c]) =
                        __floats2half2_rn(v1.x, v1.y);
            }
        }
    }
}

// ---------------- pooling + logits ----------------
__global__ void k_pool() {
    int g = blockIdx.x;
    int t = threadIdx.x;
    int s0 = g_goff[g], s1 = g_goff[g + 1];
    float acc = 0.f;
    for (int n = s0; n < s1; n++) acc += g_latent[(size_t)n * 256 + t];
    float cnt = (float)(s1 - s0);
    if (cnt < 1.f) cnt = 1.f;
    g_pooled[g * 256 + t] = acc / cnt;
}
__global__ void k_logits(const float* __restrict__ w_lin, const float* __restrict__ b_lin,
                         float* __restrict__ out) {
    int idx = blockIdx.x * blockDim.x + threadIdx.x;
    if (idx >= NG * 7) return;
    int g = idx / 7, o = idx % 7;
    float acc = b_lin[o];
    for (int k = 0; k < 256; k++) acc += g_pooled[g * 256 + k] * w_lin[k * 7 + o];
    out[g * 7 + o] = acc;
}

// ---------------- launch ----------------
extern "C" void kernel_launch(void* const* d_in, const int* in_sizes, int n_in,
                              void* d_out, int out_size) {
    const int*   x       = (const int*)d_in[0];
    const int*   ei      = (const int*)d_in[1];
    const int*   batch   = (const int*)d_in[2];
    const float* emb     = (const float*)d_in[3];
    const float* w1_rel  = (const float*)d_in[4];
    const float* w1_root = (const float*)d_in[5];
    const float* b1      = (const float*)d_in[6];
    const float* w2_rel  = (const float*)d_in[7];
    const float* w2_root = (const float*)d_in[8];
    const float* b2      = (const float*)d_in[9];
    const float* we_rel  = (const float*)d_in[10];
    const float* we_root = (const float*)d_in[11];
    const float* be      = (const float*)d_in[12];
    const float* wd_rel  = (const float*)d_in[13];
    const float* wd_root = (const float*)d_in[14];
    const float* bd      = (const float*)d_in[15];
    const float* w_lin   = (const float*)d_in[16];
    const float* b_lin   = (const float*)d_in[17];

    const int* src = ei;
    const int* dst = ei + NE;

    float* out_f  = (float*)d_out;
    float* logits = out_f;
    float* recon  = out_f + NG * 7;
    float* orig   = out_f + NG * 7 + (size_t)NN * 1024;

    cudaFuncSetAttribute(gemm_tc, cudaFuncAttributeMaxDynamicSharedMemorySize, GEMM_SMEM);

    // scratch symbol addresses
    float *enc, *a256, *lat;
    cudaGetSymbolAddress((void**)&enc,  g_enc);
    cudaGetSymbolAddress((void**)&a256, g_aggr256);
    cudaGetSymbolAddress((void**)&lat,  g_latent);
    __half *ac2, *ae, *ad;
    cudaGetSymbolAddress((void**)&ac2, g_Ac2);
    cudaGetSymbolAddress((void**)&ae,  g_Ae);
    cudaGetSymbolAddress((void**)&ad,  g_Ad);
    __half *bc2h, *bc2l, *beh, *bel, *bdh, *bdl;
    cudaGetSymbolAddress((void**)&bc2h, g_Bc2h);
    cudaGetSymbolAddress((void**)&bc2l, g_Bc2l);
    cudaGetSymbolAddress((void**)&beh,  g_Beh);
    cudaGetSymbolAddress((void**)&bel,  g_Bel);
    cudaGetSymbolAddress((void**)&bdh,  g_Bdh);
    cudaGetSymbolAddress((void**)&bdl,  g_Bdl);

    // CSR + graph offsets
    k_zero_counts<<<(NN + 255) / 256, 256>>>();
    k_hist_edges<<<(NE + 255) / 256, 256>>>(dst);
    k_hist_nodes<<<(NN + 255) / 256, 256>>>(batch);
    k_scan_part<<<NBLK, 1024>>>();
    k_scan_tot<<<1, 32>>>();
    k_scan_add<<<(NN + 255) / 256, 256>>>();
    k_scan_graphs<<<1, NG>>>();
    k_copy_cursor<<<(NN + 255) / 256, 256>>>();
    k_scatter<<<(NE + 255) / 256, 256>>>(src, dst);

    // weight prep (transpose + fp16 hi/lo split, K-major concat layouts)
    k_prep<<<dim3(128 / 32, 1024 / 32), dim3(32, 8)>>>(w2_rel, w2_root, 128, 1024, 64, 0, bc2h, bc2l);
    k_prep<<<dim3(1024 / 32, 512 / 32), dim3(32, 8)>>>(we_rel, we_root, 1024, 512, 256, 1, beh, bel);
    k_prep<<<dim3(512 / 32, 1024 / 32), dim3(32, 8)>>>(wd_rel, wd_root, 512, 1024, 256, 0, bdh, bdl);

    // conv1
    k_conv1<<<(NN + 3) / 4, 128>>>(x, emb, w1_rel, w1_root, b1);
    k_agg64<<<(NN + 3) / 4, 128>>>();

    int gy = (NN + BM - 1) / BM;  // 391

    // conv2: [aggr64 | h1] @ Bc2 -> orig (fp32) + fp16 copy for enc A
    gemm_tc<<<dim3(1024 / BN, gy), 256, GEMM_SMEM>>>(
        ac2, 128, bc2h, bc2l, b2, orig, ae, 1024, NN, 1024, 128, 1);

    // enc: orig @ [we_rel | we_root] -> g_enc (raw fp32)
    gemm_tc<<<dim3(512 / BN, gy), 256, GEMM_SMEM>>>(
        ae, 1024, beh, bel, nullptr, enc, nullptr, 0, NN, 512, 1024, 0);
    k_agg256<<<NN, 256>>>(enc, 512, a256, nullptr, 0, 0);
    k_enc_finish<<<(NN * 256 + 255) / 256, 256>>>(be);

    // dec: aggregate latent -> fp16 into Ad cols 0..255, then GEMM
    k_agg256<<<NN, 256>>>(lat, 256, nullptr, ad, 512, 0);
    gemm_tc<<<dim3(1024 / BN, gy), 256, GEMM_SMEM>>>(
        ad, 512, bdh, bdl, bd, recon, nullptr, 0, NN, 1024, 512, 1);

    // pooling + logits
    k_pool<<<NG, 256>>>();
    k_logits<<<(NG * 7 + 255) / 256, 256>>>(w_lin, b_lin, logits);
}

// round 16
// speedup vs baseline: 3.5779x; 1.3307x over previous
#include <cuda_runtime.h>
#include <cuda_fp16.h>
#include <cstdint>

#define NN 50000
#define NE 800000
#define NG 256
#define NBLK 49   // ceil(NN/1024)
#define LRELU(v) ((v) >= 0.f ? (v) : 0.01f * (v))

// ---------------- scratch (static device allocations; no cudaMalloc) ----------------
__device__ int   g_deg[NN];
__device__ int   g_off[NN + 1];
__device__ int   g_cursor[NN];
__device__ int   g_perm[NE];
__device__ int   g_btot[NBLK];
__device__ int   g_gcount[NG];
__device__ int   g_goff[NG + 1];
__device__ float g_h1[(size_t)NN * 64];
__device__ float g_enc[(size_t)NN * 512];      // enc GEMM out: cols 0-255 rel-proj, 256-511 root-proj
__device__ float g_aggr256[(size_t)NN * 256];
__device__ float g_latent[(size_t)NN * 256];
__device__ float g_pooled[NG * 256];
// fp16 A operands (row-major, K contiguous)
__device__ __half g_Ac2[(size_t)NN * 128];     // [aggr64 | h1]
__device__ __half g_Ae[(size_t)NN * 1024];     // orig
__device__ __half g_Ad[(size_t)NN * 512];      // [adec | latent]
// transposed fp16 weights (K-major: [N, Ktot])
__device__ __half g_Bc2[1024 * 128];
__device__ __half g_Be[512 * 1024];
__device__ __half g_Bd[1024 * 512];

// ---------------- helpers ----------------
__device__ __forceinline__ uint32_t smem_u32(const void* p) {
    uint32_t a;
    asm("{ .reg .u64 t; cvta.to.shared.u64 t, %1; cvt.u32.u64 %0, t; }" : "=r"(a) : "l"(p));
    return a;
}
__device__ __forceinline__ void ldsm_x4(uint32_t& r0, uint32_t& r1, uint32_t& r2, uint32_t& r3,
                                        uint32_t addr) {
    asm volatile("ldmatrix.sync.aligned.m8n8.x4.shared.b16 {%0,%1,%2,%3}, [%4];"
                 : "=r"(r0), "=r"(r1), "=r"(r2), "=r"(r3) : "r"(addr));
}
__device__ __forceinline__ void mma_f16(float* c, const uint32_t* a, const uint32_t* b) {
    asm volatile(
        "mma.sync.aligned.m16n8k16.row.col.f32.f16.f16.f32 "
        "{%0,%1,%2,%3}, {%4,%5,%6,%7}, {%8,%9}, {%0,%1,%2,%3};"
        : "+f"(c[0]), "+f"(c[1]), "+f"(c[2]), "+f"(c[3])
        : "r"(a[0]), "r"(a[1]), "r"(a[2]), "r"(a[3]), "r"(b[0]), "r"(b[1]));
}
__device__ __forceinline__ void cp16(uint32_t dst, const void* src, bool ok) {
    int sz = ok ? 16 : 0;
    asm volatile("cp.async.cg.shared.global [%0], [%1], 16, %2;"
                 :: "r"(dst), "l"(src), "r"(sz) : "memory");
}

// ---------------- CSR construction ----------------
__global__ void k_zero_counts() {
    int i = blockIdx.x * blockDim.x + threadIdx.x;
    if (i < NN) g_deg[i] = 0;
    if (i < NG) g_gcount[i] = 0;
}
__global__ void k_hist_edges(const int* __restrict__ dst) {
    int e = blockIdx.x * blockDim.x + threadIdx.x;
    if (e < NE) atomicAdd(&g_deg[dst[e]], 1);
}
__global__ void k_hist_nodes(const int* __restrict__ batch) {
    int i = blockIdx.x * blockDim.x + threadIdx.x;
    if (i < NN) atomicAdd(&g_gcount[batch[i]], 1);
}
// multi-block scan: partial per-block inclusive scans + block totals
__global__ void k_scan_part() {
    __shared__ int wsum[32];
    int t = threadIdx.x, lane = t & 31, w = t >> 5;
    int idx = blockIdx.x * 1024 + t;
    int v = (idx < NN) ? g_deg[idx] : 0;
    int sc = v;
#pragma unroll
    for (int o = 1; o < 32; o <<= 1) { int u = __shfl_up_sync(~0u, sc, o); if (lane >= o) sc += u; }
    if (lane == 31) wsum[w] = sc;
    __syncthreads();
    if (w == 0) {
        int s = wsum[lane];
#pragma unroll
        for (int o = 1; o < 32; o <<= 1) { int u = __shfl_up_sync(~0u, s, o); if (lane >= o) s += u; }
        wsum[lane] = s;
    }
    __syncthreads();
    int inc = ((w > 0) ? wsum[w - 1] : 0) + sc;
    if (idx < NN) g_off[idx + 1] = inc;
    if (t == 1023) g_btot[blockIdx.x] = inc;
}
__global__ void k_scan_tot() {  // one warp scans NBLK block totals -> exclusive
    int lane = threadIdx.x;
    int a = (lane < NBLK) ? g_btot[lane] : 0;
    int b = (lane + 32 < NBLK) ? g_btot[lane + 32] : 0;
    int sa = a, sb = b;
#pragma unroll
    for (int o = 1; o < 32; o <<= 1) { int u = __shfl_up_sync(~0u, sa, o); if (lane >= o) sa += u; }
    int T = __shfl_sync(~0u, sa, 31);
#pragma unroll
    for (int o = 1; o < 32; o <<= 1) { int u = __shfl_up_sync(~0u, sb, o); if (lane >= o) sb += u; }
    if (lane < NBLK) g_btot[lane] = sa - a;
    if (lane + 32 < NBLK) g_btot[lane + 32] = T + sb - b;
}
__global__ void k_scan_add() {
    int i = blockIdx.x * blockDim.x + threadIdx.x;
    if (i < NN) g_off[i + 1] += g_btot[i >> 10];
    if (i == 0) g_off[0] = 0;
}
__global__ void k_scan_graphs() {
    __shared__ int s[NG];
    int t = threadIdx.x;
    s[t] = g_gcount[t];
    __syncthreads();
    for (int off = 1; off < NG; off <<= 1) {
        int tv = (t >= off) ? s[t - off] : 0;
        __syncthreads();
        s[t] += tv;
        __syncthreads();
    }
    g_goff[t + 1] = s[t];
    if (t == 0) g_goff[0] = 0;
}
__global__ void k_copy_cursor() {
    int i = blockIdx.x * blockDim.x + threadIdx.x;
    if (i < NN) g_cursor[i] = g_off[i];
}
__global__ void k_scatter(const int* __restrict__ src, const int* __restrict__ dst) {
    int e = blockIdx.x * blockDim.x + threadIdx.x;
    if (e < NE) {
        int d = dst[e];
        int p = atomicAdd(&g_cursor[d], 1);
        g_perm[p] = src[e];
    }
}

// ---------------- conv1: warp per node, lanes parallel over edges ----------------
__global__ void k_conv1(const int* __restrict__ x, const float* __restrict__ emb,
                        const float* __restrict__ w_rel, const float* __restrict__ w_root,
                        const float* __restrict__ b1) {
    __shared__ float embs[32];
    int t = threadIdx.x;  // 128
    if (t < 30) embs[t] = emb[t];
    __syncthreads();
    int w = t >> 5, lane = t & 31;
    int i = blockIdx.x * 4 + w;
    if (i >= NN) return;
    int s0 = g_off[i], s1 = g_off[i + 1];
    float a0 = 0.f, a1 = 0.f, a2 = 0.f;
    for (int e = s0 + lane; e < s1; e += 32) {
        int lab = x[g_perm[e]] * 3;
        a0 += embs[lab];
        a1 += embs[lab + 1];
        a2 += embs[lab + 2];
    }
#pragma unroll
    for (int o = 16; o; o >>= 1) {
        a0 += __shfl_down_sync(~0u, a0, o);
        a1 += __shfl_down_sync(~0u, a1, o);
        a2 += __shfl_down_sync(~0u, a2, o);
    }
    a0 = __shfl_sync(~0u, a0, 0);
    a1 = __shfl_sync(~0u, a1, 0);
    a2 = __shfl_sync(~0u, a2, 0);
    int lab = x[i] * 3;
    float e0 = embs[lab], e1 = embs[lab + 1], e2 = embs[lab + 2];
#pragma unroll
    for (int rep = 0; rep < 2; rep++) {
        int c = lane + rep * 32;
        float v = b1[c] + a0 * w_rel[c] + a1 * w_rel[64 + c] + a2 * w_rel[128 + c]
                        + e0 * w_root[c] + e1 * w_root[64 + c] + e2 * w_root[128 + c];
        float r = LRELU(v);
        g_h1[(size_t)i * 64 + c] = r;
        g_Ac2[(size_t)i * 128 + 64 + c] = __float2half_rn(r);
    }
}

// ---------------- aggregations ----------------
__global__ void k_agg64() {  // aggregate h1 (fp32), write fp16 into Ac2 cols 0..63
    int w = threadIdx.x >> 5, lane = threadIdx.x & 31;
    int i = blockIdx.x * 4 + w;
    if (i >= NN) return;
    const float2* h = reinterpret_cast<const float2*>(g_h1);
    float2 acc = make_float2(0.f, 0.f);
    int s0 = g_off[i], s1 = g_off[i + 1];
    for (int e = s0; e < s1; e++) {
        float2 v = h[(size_t)g_perm[e] * 32 + lane];
        acc.x += v.x;
        acc.y += v.y;
    }
    reinterpret_cast<__half2*>(g_Ac2)[(size_t)i * 64 + lane] =
        __floats2half2_rn(acc.x, acc.y);
}
// 256-wide aggregation (fp32 input): optional fp32 out, optional fp16 out
__global__ void k_agg256(const float* __restrict__ in, int ldin, float* __restrict__ f32out,
                         __half* __restrict__ oh, int ldo, int coff) {
    int i = blockIdx.x;
    int t = threadIdx.x;  // 256
    int s0 = g_off[i], s1 = g_off[i + 1];
    float acc = 0.f;
    for (int e = s0; e < s1; e++) acc += in[(size_t)g_perm[e] * ldin + t];
    if (f32out) f32out[(size_t)i * 256 + t] = acc;
    if (oh) oh[(size_t)i * ldo + coff + t] = __float2half_rn(acc);
}
// 256-wide aggregation (fp16 input, fp32 accumulate, fp16 out)
__global__ void k_agg256h(const __half* __restrict__ in, int ldin, int cin,
                          __half* __restrict__ oh, int ldo, int coff) {
    int i = blockIdx.x;
    int t = threadIdx.x;  // 256
    int s0 = g_off[i], s1 = g_off[i + 1];
    float acc = 0.f;
    for (int e = s0; e < s1; e++)
        acc += __half2float(in[(size_t)g_perm[e] * ldin + cin + t]);
    oh[(size_t)i * ldo + coff + t] = __float2half_rn(acc);
}
__global__ void k_enc_finish(const float* __restrict__ be) {
    int idx = blockIdx.x * blockDim.x + threadIdx.x;
    if (idx >= NN * 256) return;
    int i = idx >> 8, c = idx & 255;
    float v = g_enc[(size_t)i * 512 + 256 + c] + g_aggr256[idx] + be[c];
    float r = LRELU(v);
    g_latent[idx] = r;
    g_Ad[(size_t)i * 512 + 256 + c] = __float2half_rn(r);
}

// ---------------- weight transpose + fp16 round ----------------
__global__ void k_prep(const float* __restrict__ s1, const float* __restrict__ s2,
                       int Ktot, int Ntot, int split, int mode,
                       __half* __restrict__ dh) {
    __shared__ float tile[32][33];
    int k0 = blockIdx.x * 32, n0 = blockIdx.y * 32;
    int tx = threadIdx.x, ty = threadIdx.y;  // (32, 8)
#pragma unroll
    for (int r = 0; r < 32; r += 8) {
        int k = k0 + ty + r, n = n0 + tx;
        float v;
        if (mode == 0)
            v = (k < split) ? s1[(size_t)k * Ntot + n] : s2[(size_t)(k - split) * Ntot + n];
        else
            v = (n < split) ? s1[(size_t)k * split + n] : s2[(size_t)k * (Ntot - split) + (n - split)];
        tile[ty + r][tx] = v;
    }
    __syncthreads();
#pragma unroll
    for (int r = 0; r < 32; r += 8) {
        int n = n0 + ty + r, k = k0 + tx;
        dh[(size_t)n * Ktot + k] = __float2half_rn(tile[tx][ty + r]);
    }
}

// ---------------- HMMA fp16 GEMM, 3-stage cp.async pipeline ----------------
// out[M,N] = act( A[M,Ktot] @ B^T + bias ); A, B fp16.
// Block 128x128, BK=32, 256 thr, warps 4(m) x 2(n), warp tile 32x64.
#define BM 128
#define BN 128
#define BK 32
#define BKP 40                       // padded K stride (elements) -> 80B rows
#define OFF_A  0
#define OFF_B  (BM * BKP * 2)        // 10240
#define STAGE  (2 * BM * BKP * 2)    // 20480
#define NSTG 3
#define GEMM_SMEM (NSTG * STAGE)     // 61440

__global__ __launch_bounds__(256) void gemm_tc(
    const __half* __restrict__ A, int lda,
    const __half* __restrict__ B,
    const float* __restrict__ bias, float* __restrict__ out,
    __half* __restrict__ outh, int ldo,
    int M, int N, int Ktot, int act) {
    extern __shared__ char smem[];
    uint32_t uS = smem_u32(smem);
    int tid = threadIdx.x, lane = tid & 31, wid = tid >> 5;
    int wm = wid & 3, wn = wid >> 2;
    int m_base = wm * 32, n_base = wn * 64;
    int bm = blockIdx.y * BM, bn = blockIdx.x * BN;

    float acc[2][8][4];
#pragma unroll
    for (int i = 0; i < 2; i++)
#pragma unroll
        for (int j = 0; j < 8; j++)
#pragma unroll
            for (int q = 0; q < 4; q++) acc[i][j][q] = 0.f;

    // staging map: 2 threads per row, 16 cols (32B = 2x16B chunks) each
    int r = tid >> 1, c16 = (tid & 1) * 16;
    int gm = bm + r;
    bool okA = (gm < M);
    const char* pA = (const char*)(A + (size_t)(okA ? gm : 0) * lda + c16);
    const char* pB = (const char*)(B + (size_t)(bn + r) * Ktot + c16);
    uint32_t sdst = (uint32_t)((r * BKP + c16) * 2);

    auto issue = [&](int s) {
        uint32_t sb = uS + (uint32_t)(s % NSTG) * STAGE + sdst;
        size_t ko = (size_t)s * BK * 2;  // bytes
        cp16(sb + OFF_A,      pA + ko,      okA);
        cp16(sb + OFF_A + 16, pA + ko + 16, okA);
        cp16(sb + OFF_B,      pB + ko,      true);
        cp16(sb + OFF_B + 16, pB + ko + 16, true);
        asm volatile("cp.async.commit_group;" ::: "memory");
    };

    // ldmatrix lane address components
    int a_row = (lane & 15);
    int a_coff = (lane >> 4) * 8;
    int b_row = ((lane >> 4) << 3) + (lane & 7);
    int b_coff = ((lane >> 3) & 1) * 8;

    int nst = Ktot / BK;
    issue(0);
    if (nst > 1) issue(1);
    for (int s = 0; s < nst; s++) {
        if (s + 2 < nst) {
            issue(s + 2);
            asm volatile("cp.async.wait_group 2;" ::: "memory");
        } else if (s + 1 < nst) {
            asm volatile("cp.async.wait_group 1;" ::: "memory");
        } else {
            asm volatile("cp.async.wait_group 0;" ::: "memory");
        }
        __syncthreads();
        uint32_t sb = uS + (uint32_t)(s % NSTG) * STAGE;
#pragma unroll
        for (int kk = 0; kk < BK; kk += 16) {
            uint32_t a[2][4], b[8][2];
#pragma unroll
            for (int mi = 0; mi < 2; mi++) {
                uint32_t off = (uint32_t)(((m_base + mi * 16 + a_row) * BKP + kk + a_coff) * 2);
                ldsm_x4(a[mi][0], a[mi][1], a[mi][2], a[mi][3], sb + OFF_A + off);
            }
#pragma unroll
            for (int nj = 0; nj < 4; nj++) {
                uint32_t off = (uint32_t)(((n_base + nj * 16 + b_row) * BKP + kk + b_coff) * 2);
                ldsm_x4(b[2 * nj][0], b[2 * nj][1], b[2 * nj + 1][0], b[2 * nj + 1][1], sb + OFF_B + off);
            }
#pragma unroll
            for (int mi = 0; mi < 2; mi++)
#pragma unroll
                for (int ni = 0; ni < 8; ni++)
                    mma_f16(acc[mi][ni], a[mi], b[ni]);
        }
        __syncthreads();
    }

    // ---- epilogue: bias + leaky-relu; fp32 store + optional fp16 store
    int gq = lane >> 2, tg = lane & 3;
#pragma unroll
    for (int mi = 0; mi < 2; mi++) {
        int r0 = bm + m_base + mi * 16 + gq;
        int r1 = r0 + 8;
#pragma unroll
        for (int ni = 0; ni < 8; ni++) {
            int c = bn + n_base + ni * 8 + 2 * tg;
            float2 v0 = make_float2(acc[mi][ni][0], acc[mi][ni][1]);
            float2 v1 = make_float2(acc[mi][ni][2], acc[mi][ni][3]);
            if (bias) {
                float bx = bias[c], by = bias[c + 1];
                v0.x += bx; v0.y += by;
                v1.x += bx; v1.y += by;
            }
            if (act) {
                v0.x = LRELU(v0.x); v0.y = LRELU(v0.y);
                v1.x = LRELU(v1.x); v1.y = LRELU(v1.y);
            }
            if (r0 < M) {
                *reinterpret_cast<float2*>(&out[(size_t)r0 * N + c]) = v0;
                if (outh)
                    *reinterpret_cast<__half2*>(&outh[(size_t)r0 * ldo + c]) =
                        __floats2half2_rn(v0.x, v0.y);
            }
            if (r1 < M) {
                *reinterpret_cast<float2*>(&out[(size_t)r1 * N + c]) = v1;
                if (outh)
                    *reinterpret_cast<__half2*>(&outh[(size_t)r1 * ldo + c]) =
                        __floats2half2_rn(v1.x, v1.y);
            }
        }
    }
}

// ---------------- pooling + logits ----------------
__global__ void k_pool() {
    int g = blockIdx.x;
    int t = threadIdx.x;
    int s0 = g_goff[g], s1 = g_goff[g + 1];
    float acc = 0.f;
    for (int n = s0; n < s1; n++) acc += g_latent[(size_t)n * 256 + t];
    float cnt = (float)(s1 - s0);
    if (cnt < 1.f) cnt = 1.f;
    g_pooled[g * 256 + t] = acc / cnt;
}
__global__ void k_logits(const float* __restrict__ w_lin, const float* __restrict__ b_lin,
                         float* __restrict__ out) {
    int idx = blockIdx.x * blockDim.x + threadIdx.x;
    if (idx >= NG * 7) return;
    int g = idx / 7, o = idx % 7;
    float acc = b_lin[o];
    for (int k = 0; k < 256; k++) acc += g_pooled[g * 256 + k] * w_lin[k * 7 + o];
    out[g * 7 + o] = acc;
}

// ---------------- launch ----------------
extern "C" void kernel_launch(void* const* d_in, const int* in_sizes, int n_in,
                              void* d_out, int out_size) {
    const int*   x       = (const int*)d_in[0];
    const int*   ei      = (const int*)d_in[1];
    const int*   batch   = (const int*)d_in[2];
    const float* emb     = (const float*)d_in[3];
    const float* w1_rel  = (const float*)d_in[4];
    const float* w1_root = (const float*)d_in[5];
    const float* b1      = (const float*)d_in[6];
    const float* w2_rel  = (const float*)d_in[7];
    const float* w2_root = (const float*)d_in[8];
    const float* b2      = (const float*)d_in[9];
    const float* we_rel  = (const float*)d_in[10];
    const float* we_root = (const float*)d_in[11];
    const float* be      = (const float*)d_in[12];
    const float* wd_rel  = (const float*)d_in[13];
    const float* wd_root = (const float*)d_in[14];
    const float* bd      = (const float*)d_in[15];
    const float* w_lin   = (const float*)d_in[16];
    const float* b_lin   = (const float*)d_in[17];

    const int* src = ei;
    const int* dst = ei + NE;

    float* out_f  = (float*)d_out;
    float* logits = out_f;
    float* recon  = out_f + NG * 7;
    float* orig   = out_f + NG * 7 + (size_t)NN * 1024;

    cudaFuncSetAttribute(gemm_tc, cudaFuncAttributeMaxDynamicSharedMemorySize, GEMM_SMEM);

    // scratch symbol addresses
    float *enc, *a256, *lat;
    cudaGetSymbolAddress((void**)&enc,  g_enc);
    cudaGetSymbolAddress((void**)&a256, g_aggr256);
    cudaGetSymbolAddress((void**)&lat,  g_latent);
    __half *ac2, *ae, *ad;
    cudaGetSymbolAddress((void**)&ac2, g_Ac2);
    cudaGetSymbolAddress((void**)&ae,  g_Ae);
    cudaGetSymbolAddress((void**)&ad,  g_Ad);
    __half *bc2, *be16, *bd16;
    cudaGetSymbolAddress((void**)&bc2,  g_Bc2);
    cudaGetSymbolAddress((void**)&be16, g_Be);
    cudaGetSymbolAddress((void**)&bd16, g_Bd);

    // CSR + graph offsets
    k_zero_counts<<<(NN + 255) / 256, 256>>>();
    k_hist_edges<<<(NE + 255) / 256, 256>>>(dst);
    k_hist_nodes<<<(NN + 255) / 256, 256>>>(batch);
    k_scan_part<<<NBLK, 1024>>>();
    k_scan_tot<<<1, 32>>>();
    k_scan_add<<<(NN + 255) / 256, 256>>>();
    k_scan_graphs<<<1, NG>>>();
    k_copy_cursor<<<(NN + 255) / 256, 256>>>();
    k_scatter<<<(NE + 255) / 256, 256>>>(src, dst);

    // weight prep (transpose + fp16 round, K-major concat layouts)
    k_prep<<<dim3(128 / 32, 1024 / 32), dim3(32, 8)>>>(w2_rel, w2_root, 128, 1024, 64, 0, bc2);
    k_prep<<<dim3(1024 / 32, 512 / 32), dim3(32, 8)>>>(we_rel, we_root, 1024, 512, 256, 1, be16);
    k_prep<<<dim3(512 / 32, 1024 / 32), dim3(32, 8)>>>(wd_rel, wd_root, 512, 1024, 256, 0, bd16);

    // conv1
    k_conv1<<<(NN + 3) / 4, 128>>>(x, emb, w1_rel, w1_root, b1);
    k_agg64<<<(NN + 3) / 4, 128>>>();

    int gy = (NN + BM - 1) / BM;  // 391

    // conv2: [aggr64 | h1] @ Bc2 -> orig (fp32) + fp16 copy for enc A
    gemm_tc<<<dim3(1024 / BN, gy), 256, GEMM_SMEM>>>(
        ac2, 128, bc2, b2, orig, ae, 1024, NN, 1024, 128, 1);

    // enc: orig @ [we_rel | we_root] -> g_enc (raw fp32)
    gemm_tc<<<dim3(512 / BN, gy), 256, GEMM_SMEM>>>(
        ae, 1024, be16, nullptr, enc, nullptr, 0, NN, 512, 1024, 0);
    k_agg256<<<NN, 256>>>(enc, 512, a256, nullptr, 0, 0);
    k_enc_finish<<<(NN * 256 + 255) / 256, 256>>>(be);

    // dec: aggregate fp16 latent (from g_Ad cols 256..511) -> fp16 into Ad cols 0..255
    k_agg256h<<<NN, 256>>>(ad, 512, 256, ad, 512, 0);
    gemm_tc<<<dim3(1024 / BN, gy), 256, GEMM_SMEM>>>(
        ad, 512, bd16, bd, recon, nullptr, 0, NN, 1024, 512, 1);

    // pooling + logits
    k_pool<<<NG, 256>>>();
    k_logits<<<(NG * 7 + 255) / 256, 256>>>(w_lin, b_lin, logits);
}